// round 7
// baseline (speedup 1.0000x reference)
#include <cuda_runtime.h>
#include <cuda_bf16.h>
#include <stdint.h>

#define DD 128
#define NMAX 50176
#define EMAX 819200

// ---------------- scratch (static device globals; no allocation) ------------
__device__ int   g_cnt   [NMAX];        // in-degree counts (excl self loop)
__device__ int   g_cnt2  [NMAX];        // csr fill cursors
__device__ int   g_rowptr[NMAX + 1];    // CSR row offsets
__device__ int   g_csr   [EMAX];        // CSR src indices
__device__ int   g_bsum  [256];         // scan block sums
__device__ int   g_boff  [256];         // scan block offsets
__device__ float g_dis   [NMAX];        // 1/sqrt(deg)
__device__ float g_hw    [NMAX * DD];   // x@W1, then h1@W2
__device__ float g_agg   [NMAX * DD];   // conv1 output (pre-BN)
__device__ float g_bn    [2 * DD];      // col sums / sumsq
__device__ float g_sA    [DD];          // gamma*rstd
__device__ float g_sB    [DD];          // beta - mu*gamma*rstd

// ---------------- in-degree histogram over dst -------------------------------
__global__ void k_deg(const int* __restrict__ dst, int E) {
    int e = blockIdx.x * blockDim.x + threadIdx.x;
    if (e < E) atomicAdd(&g_cnt[dst[e]], 1);
}

// ---------------- scan phase 1: per-block exclusive scan + block sum + dis ---
__global__ void __launch_bounds__(256) k_scan1(int n) {
    __shared__ int s[256];
    int t = threadIdx.x;
    int i = blockIdx.x * 256 + t;
    int v = (i < n) ? g_cnt[i] : 0;
    if (i < n) g_dis[i] = rsqrtf((float)(1 + v));
    s[t] = v;
    __syncthreads();
#pragma unroll
    for (int off = 1; off < 256; off <<= 1) {
        int u = (t >= off) ? s[t - off] : 0;
        __syncthreads();
        s[t] += u;
        __syncthreads();
    }
    if (i <= n) g_rowptr[i] = s[t] - v;
    if (t == 255) g_bsum[blockIdx.x] = s[255];
}

// ---------------- scan phase 2: scan block sums (<=256 blocks) ---------------
__global__ void __launch_bounds__(256) k_scan2(int nb, int n) {
    __shared__ int s[256];
    int t = threadIdx.x;
    int v = (t < nb) ? g_bsum[t] : 0;
    s[t] = v;
    __syncthreads();
#pragma unroll
    for (int off = 1; off < 256; off <<= 1) {
        int u = (t >= off) ? s[t - off] : 0;
        __syncthreads();
        s[t] += u;
        __syncthreads();
    }
    if (t < nb) g_boff[t] = s[t] - v;
    if (t == 255) g_rowptr[n] = s[255];
}

// ---------------- scan phase 3: add block offsets -----------------------------
__global__ void __launch_bounds__(256) k_scan3(int n) {
    int i = blockIdx.x * 256 + threadIdx.x;
    if (i < n) g_rowptr[i] += g_boff[blockIdx.x];
}

// ---------------- CSR fill: slot per (dst, in-edge) ---------------------------
__global__ void k_fill(const int* __restrict__ src,
                       const int* __restrict__ dst, int E) {
    int e = blockIdx.x * blockDim.x + threadIdx.x;
    if (e >= E) return;
    int d = dst[e];
    int pos = g_rowptr[d] + atomicAdd(&g_cnt2[d], 1);
    g_csr[pos] = src[e];
}

// ---------------- tensor-core GEMM: C[n,128] = A'[n,128] @ W[128,128] --------
// bf16 split (A=Ah+Al, W=Wh+Wl), 3-term mma.sync m16n8k16 with fp32 accum.
// Block: 64 rows x 128 cols, 8 warps (warp tile 16x64). K in 2 chunks of 64.
// smem: sAh/sAl [64][72] bf16, sWh/sWl [128][72] bf16 (transposed [n][k]).
#define PAD 72
#define SMEM_T ((2 * 64 * PAD + 2 * 128 * PAD) * 2)

__device__ __forceinline__ void mma_bf16(float* d, uint32_t a0, uint32_t a1,
                                         uint32_t a2, uint32_t a3,
                                         uint32_t b0, uint32_t b1) {
    asm volatile(
        "mma.sync.aligned.m16n8k16.row.col.f32.bf16.bf16.f32 "
        "{%0,%1,%2,%3}, {%4,%5,%6,%7}, {%8,%9}, {%0,%1,%2,%3};"
        : "+f"(d[0]), "+f"(d[1]), "+f"(d[2]), "+f"(d[3])
        : "r"(a0), "r"(a1), "r"(a2), "r"(a3), "r"(b0), "r"(b1));
}

__device__ __forceinline__ void split_bf16(float v, __nv_bfloat16& h,
                                           __nv_bfloat16& l) {
    h = __float2bfloat16(v);
    l = __float2bfloat16(v - __bfloat162float(h));
}

__global__ void __launch_bounds__(256) k_gemm(const float* __restrict__ A,
                                              const float* __restrict__ W,
                                              float* __restrict__ C, int n,
                                              int fuseBN) {
    extern __shared__ __nv_bfloat16 sm[];
    __nv_bfloat16* sAh = sm;                    // [64][PAD]
    __nv_bfloat16* sAl = sAh + 64 * PAD;
    __nv_bfloat16* sWh = sAl + 64 * PAD;        // [128][PAD] transposed [n][k]
    __nv_bfloat16* sWl = sWh + 128 * PAD;

    const int tid  = threadIdx.x;
    const int lane = tid & 31;
    const int w    = tid >> 5;
    const int g    = lane >> 2;      // 0..7
    const int t    = lane & 3;       // 0..3
    const int row0 = blockIdx.x * 64;
    const int rowb = (w & 3) * 16;   // warp row offset in tile
    const int colb = (w >> 2) * 64;  // warp col offset in tile

    float acc[8][4];
#pragma unroll
    for (int nt = 0; nt < 8; nt++)
#pragma unroll
        for (int q = 0; q < 4; q++) acc[nt][q] = 0.f;

    const float4* A4 = (const float4*)A;
    const float4* W4 = (const float4*)W;

    for (int kc = 0; kc < 2; kc++) {
        __syncthreads();
        // ---- stage A chunk [64 rows][64 k] split into bf16 hi/lo ----
#pragma unroll
        for (int i = 0; i < 4; i++) {
            int idx = tid + i * 256;          // 1024 float4
            int r = idx >> 4, c = idx & 15;   // r:0..63, c:0..15 (float4)
            int gr = row0 + r;
            float4 v = (gr < n) ? A4[(size_t)gr * 32 + kc * 16 + c]
                                : make_float4(0.f, 0.f, 0.f, 0.f);
            if (fuseBN) {
                float4 sa = ((const float4*)g_sA)[kc * 16 + c];
                float4 sb = ((const float4*)g_sB)[kc * 16 + c];
                v.x = fmaxf(fmaf(v.x, sa.x, sb.x), 0.f);
                v.y = fmaxf(fmaf(v.y, sa.y, sb.y), 0.f);
                v.z = fmaxf(fmaf(v.z, sa.z, sb.z), 0.f);
                v.w = fmaxf(fmaf(v.w, sa.w, sb.w), 0.f);
            }
            int o = r * PAD + c * 4;
            split_bf16(v.x, sAh[o + 0], sAl[o + 0]);
            split_bf16(v.y, sAh[o + 1], sAl[o + 1]);
            split_bf16(v.z, sAh[o + 2], sAl[o + 2]);
            split_bf16(v.w, sAh[o + 3], sAl[o + 3]);
        }
        // ---- stage W chunk [64 k][128 n] transposed into sW[n][k] hi/lo ----
#pragma unroll
        for (int i = 0; i < 8; i++) {
            int idx = tid + i * 256;          // 2048 float4
            int r  = idx >> 5, c4 = idx & 31; // r = k-local 0..63
            float4 v = W4[(size_t)(kc * 64 + r) * 32 + c4];
            split_bf16(v.x, sWh[(c4 * 4 + 0) * PAD + r], sWl[(c4 * 4 + 0) * PAD + r]);
            split_bf16(v.y, sWh[(c4 * 4 + 1) * PAD + r], sWl[(c4 * 4 + 1) * PAD + r]);
            split_bf16(v.z, sWh[(c4 * 4 + 2) * PAD + r], sWl[(c4 * 4 + 2) * PAD + r]);
            split_bf16(v.w, sWh[(c4 * 4 + 3) * PAD + r], sWl[(c4 * 4 + 3) * PAD + r]);
        }
        __syncthreads();

        // ---- compute: 4 k-frags of 16 ----
#pragma unroll
        for (int kf = 0; kf < 4; kf++) {
            int kb = kf * 16 + t * 2;
            uint32_t ah0 = *(const uint32_t*)&sAh[(rowb + g) * PAD + kb];
            uint32_t ah1 = *(const uint32_t*)&sAh[(rowb + g + 8) * PAD + kb];
            uint32_t ah2 = *(const uint32_t*)&sAh[(rowb + g) * PAD + kb + 8];
            uint32_t ah3 = *(const uint32_t*)&sAh[(rowb + g + 8) * PAD + kb + 8];
            uint32_t al0 = *(const uint32_t*)&sAl[(rowb + g) * PAD + kb];
            uint32_t al1 = *(const uint32_t*)&sAl[(rowb + g + 8) * PAD + kb];
            uint32_t al2 = *(const uint32_t*)&sAl[(rowb + g) * PAD + kb + 8];
            uint32_t al3 = *(const uint32_t*)&sAl[(rowb + g + 8) * PAD + kb + 8];
#pragma unroll
            for (int nt = 0; nt < 8; nt++) {
                int nrow = (colb + nt * 8 + g) * PAD + kf * 16 + t * 2;
                uint32_t bh0 = *(const uint32_t*)&sWh[nrow];
                uint32_t bh1 = *(const uint32_t*)&sWh[nrow + 8];
                uint32_t bl0 = *(const uint32_t*)&sWl[nrow];
                uint32_t bl1 = *(const uint32_t*)&sWl[nrow + 8];
                mma_bf16(acc[nt], ah0, ah1, ah2, ah3, bh0, bh1);
                mma_bf16(acc[nt], ah0, ah1, ah2, ah3, bl0, bl1);
                mma_bf16(acc[nt], al0, al1, al2, al3, bh0, bh1);
            }
        }
    }

    // ---- epilogue: write fp32 ----
    int r0 = row0 + rowb + g;
    int r1 = r0 + 8;
#pragma unroll
    for (int nt = 0; nt < 8; nt++) {
        int cc = colb + nt * 8 + t * 2;
        if (r0 < n) {
            float2 v = make_float2(acc[nt][0], acc[nt][1]);
            *(float2*)&C[(size_t)r0 * DD + cc] = v;
        }
        if (r1 < n) {
            float2 v = make_float2(acc[nt][2], acc[nt][3]);
            *(float2*)&C[(size_t)r1 * DD + cc] = v;
        }
    }
}

// ---------------- CSR gather: one warp per destination node ------------------
__global__ void __launch_bounds__(256) k_gather(const float* __restrict__ hw,
                                                const float* __restrict__ bias,
                                                const float* __restrict__ agg,
                                                float* __restrict__ outbuf,
                                                int n, int skip) {
    int d = (blockIdx.x * blockDim.x + threadIdx.x) >> 5;
    int lane = threadIdx.x & 31;
    if (d >= n) return;

    const float4* hw4 = (const float4*)hw;
    float invd = g_dis[d];
    float sw = invd * invd;

    float4 acc = ((const float4*)bias)[lane];
    float4 hd = hw4[(size_t)d * 32 + lane];
    acc.x = fmaf(hd.x, sw, acc.x);
    acc.y = fmaf(hd.y, sw, acc.y);
    acc.z = fmaf(hd.z, sw, acc.z);
    acc.w = fmaf(hd.w, sw, acc.w);
    if (skip) {
        float4 a  = ((const float4*)agg)[(size_t)d * 32 + lane];
        float4 sa = ((const float4*)g_sA)[lane];
        float4 sb = ((const float4*)g_sB)[lane];
        acc.x += fmaxf(fmaf(a.x, sa.x, sb.x), 0.f);
        acc.y += fmaxf(fmaf(a.y, sa.y, sb.y), 0.f);
        acc.z += fmaxf(fmaf(a.z, sa.z, sb.z), 0.f);
        acc.w += fmaxf(fmaf(a.w, sa.w, sb.w), 0.f);
    }

    int j   = g_rowptr[d];
    int end = g_rowptr[d + 1];
    for (; j + 3 < end; j += 4) {
        int s0 = g_csr[j],     s1 = g_csr[j + 1];
        int s2 = g_csr[j + 2], s3 = g_csr[j + 3];
        float w0 = g_dis[s0] * invd, w1 = g_dis[s1] * invd;
        float w2 = g_dis[s2] * invd, w3 = g_dis[s3] * invd;
        float4 v0 = hw4[(size_t)s0 * 32 + lane];
        float4 v1 = hw4[(size_t)s1 * 32 + lane];
        float4 v2 = hw4[(size_t)s2 * 32 + lane];
        float4 v3 = hw4[(size_t)s3 * 32 + lane];
        acc.x = fmaf(v0.x, w0, fmaf(v1.x, w1, fmaf(v2.x, w2, fmaf(v3.x, w3, acc.x))));
        acc.y = fmaf(v0.y, w0, fmaf(v1.y, w1, fmaf(v2.y, w2, fmaf(v3.y, w3, acc.y))));
        acc.z = fmaf(v0.z, w0, fmaf(v1.z, w1, fmaf(v2.z, w2, fmaf(v3.z, w3, acc.z))));
        acc.w = fmaf(v0.w, w0, fmaf(v1.w, w1, fmaf(v2.w, w2, fmaf(v3.w, w3, acc.w))));
    }
    for (; j < end; ++j) {
        int s = g_csr[j];
        float w = g_dis[s] * invd;
        float4 v = hw4[(size_t)s * 32 + lane];
        acc.x = fmaf(v.x, w, acc.x);
        acc.y = fmaf(v.y, w, acc.y);
        acc.z = fmaf(v.z, w, acc.z);
        acc.w = fmaf(v.w, w, acc.w);
    }
    ((float4*)outbuf)[(size_t)d * 32 + lane] = acc;
}

// ---------------- BN column stats: sum & sumsq over rows ---------------------
__global__ void k_bnstats(const float* __restrict__ agg, int n) {
    int c = threadIdx.x;  // 128 threads
    float s = 0.f, sq = 0.f;
    for (int r = blockIdx.x; r < n; r += gridDim.x) {
        float v = agg[(size_t)r * DD + c];
        s += v;
        sq = fmaf(v, v, sq);
    }
    atomicAdd(&g_bn[c], s);
    atomicAdd(&g_bn[DD + c], sq);
}

__global__ void k_bnfinal(const float* __restrict__ gamma,
                          const float* __restrict__ beta, float inv_n) {
    int c = threadIdx.x;
    float mu = g_bn[c] * inv_n;
    float var = g_bn[DD + c] * inv_n - mu * mu;
    float rstd = rsqrtf(var + 1e-5f);
    float a = gamma[c] * rstd;
    g_sA[c] = a;
    g_sB[c] = beta[c] - mu * a;
}

// ============================================================================
extern "C" void kernel_launch(void* const* d_in, const int* in_sizes, int n_in,
                              void* d_out, int out_size) {
    const float* x     = (const float*)d_in[0];
    const int*   ei    = (const int*)d_in[1];     // int32 edge_index
    const float* W1    = (const float*)d_in[2];
    const float* b1    = (const float*)d_in[3];
    const float* W2    = (const float*)d_in[4];
    const float* b2    = (const float*)d_in[5];
    const float* gamma = (const float*)d_in[6];
    const float* beta  = (const float*)d_in[7];
    float*       out   = (float*)d_out;

    const int n = in_sizes[0] / DD;
    const int E = in_sizes[1] / 2;
    const int* src = ei;
    const int* dst = ei + E;

    static int inited = 0;
    static cudaStream_t s2;
    static cudaEvent_t evFork, evJoin;
    static void *p_cnt, *p_cnt2, *p_bn, *p_hw, *p_agg;
    if (!inited) {
        cudaFuncSetAttribute(k_gemm, cudaFuncAttributeMaxDynamicSharedMemorySize,
                             SMEM_T);
        cudaStreamCreateWithFlags(&s2, cudaStreamNonBlocking);
        cudaEventCreateWithFlags(&evFork, cudaEventDisableTiming);
        cudaEventCreateWithFlags(&evJoin, cudaEventDisableTiming);
        cudaGetSymbolAddress(&p_cnt,  g_cnt);
        cudaGetSymbolAddress(&p_cnt2, g_cnt2);
        cudaGetSymbolAddress(&p_bn,   g_bn);
        cudaGetSymbolAddress(&p_hw,   g_hw);
        cudaGetSymbolAddress(&p_agg,  g_agg);
        inited = 1;
    }
    float* hw  = (float*)p_hw;
    float* agg = (float*)p_agg;

    const int TB = 256;
    const int n_grid    = (n + TB - 1) / TB;
    const int e_grid    = (E + TB - 1) / TB;
    const int gemm_grid = (n + 63) / 64;
    const int gat_grid  = (n * 32 + TB - 1) / TB;   // warp per node

    // ---- fork: CSR build on s2, overlapped with GEMM1 on the main stream ----
    cudaEventRecord(evFork, 0);
    cudaStreamWaitEvent(s2, evFork, 0);
    cudaMemsetAsync(p_cnt,  0, (size_t)n * 4, s2);
    cudaMemsetAsync(p_cnt2, 0, (size_t)n * 4, s2);
    cudaMemsetAsync(p_bn,   0, 2 * DD * 4, s2);
    k_deg  <<<e_grid, TB, 0, s2>>>(dst, E);
    k_scan1<<<n_grid, TB, 0, s2>>>(n);
    k_scan2<<<1,      TB, 0, s2>>>(n_grid, n);
    k_scan3<<<n_grid, TB, 0, s2>>>(n);
    k_fill <<<e_grid, TB, 0, s2>>>(src, dst, E);
    cudaEventRecord(evJoin, s2);

    // ---- layer 1 (main stream) ----
    k_gemm<<<gemm_grid, TB, SMEM_T>>>(x, W1, hw, n, 0);
    cudaStreamWaitEvent(0, evJoin, 0);   // join CSR before gather
    k_gather<<<gat_grid, TB>>>(hw, b1, nullptr, agg, n, 0);
    k_bnstats<<<512, DD>>>(agg, n);
    k_bnfinal<<<1, DD>>>(gamma, beta, 1.0f / (float)n);

    // ---- layer 2: conv on relu(BN(agg)) on the fly; out = h1 + h2 ----
    k_gemm<<<gemm_grid, TB, SMEM_T>>>(agg, W2, hw, n, 1);
    k_gather<<<gat_grid, TB>>>(hw, b2, agg, out, n, 1);
}

// round 8
// speedup vs baseline: 1.3524x; 1.3524x over previous
#include <cuda_runtime.h>
#include <cuda_fp16.h>
#include <stdint.h>

#define DD 128
#define NMAX 50176
#define EMAX 819200

// ---------------- scratch (static device globals; no allocation) ------------
__device__ int   g_cnt   [NMAX];
__device__ int   g_cnt2  [NMAX];
__device__ int   g_rowptr[NMAX + 1];
__device__ int   g_csr   [EMAX];
__device__ int   g_bsum  [256];
__device__ int   g_boff  [256];
__device__ float g_dis   [NMAX];
__device__ float g_hw    [NMAX * DD];
__device__ float g_agg   [NMAX * DD];
__device__ float g_bn    [2 * DD];
__device__ float g_sA    [DD];
__device__ float g_sB    [DD];
__device__ uint2 g_Wsp   [2 * DD * 64];   // [layer][n][kp] fp16x2 (hi, lo)

// ---------------- in-degree histogram over dst -------------------------------
__global__ void k_deg(const int* __restrict__ dst, int E) {
    int e = blockIdx.x * blockDim.x + threadIdx.x;
    if (e < E) atomicAdd(&g_cnt[dst[e]], 1);
}

// ---------------- scan phase 1: exclusive block scan + block sum + dis -------
__global__ void __launch_bounds__(256) k_scan1(int n) {
    __shared__ int s[256];
    int t = threadIdx.x;
    int i = blockIdx.x * 256 + t;
    int v = (i < n) ? g_cnt[i] : 0;
    if (i < n) g_dis[i] = rsqrtf((float)(1 + v));
    s[t] = v;
    __syncthreads();
#pragma unroll
    for (int off = 1; off < 256; off <<= 1) {
        int u = (t >= off) ? s[t - off] : 0;
        __syncthreads();
        s[t] += u;
        __syncthreads();
    }
    if (i <= n) g_rowptr[i] = s[t] - v;
    if (t == 255) g_bsum[blockIdx.x] = s[255];
}

__global__ void __launch_bounds__(256) k_scan2(int nb, int n) {
    __shared__ int s[256];
    int t = threadIdx.x;
    int v = (t < nb) ? g_bsum[t] : 0;
    s[t] = v;
    __syncthreads();
#pragma unroll
    for (int off = 1; off < 256; off <<= 1) {
        int u = (t >= off) ? s[t - off] : 0;
        __syncthreads();
        s[t] += u;
        __syncthreads();
    }
    if (t < nb) g_boff[t] = s[t] - v;
    if (t == 255) g_rowptr[n] = s[255];
}

__global__ void __launch_bounds__(256) k_scan3(int n) {
    int i = blockIdx.x * 256 + threadIdx.x;
    if (i < n) g_rowptr[i] += g_boff[blockIdx.x];
}

__global__ void k_fill(const int* __restrict__ src,
                       const int* __restrict__ dst, int E) {
    int e = blockIdx.x * blockDim.x + threadIdx.x;
    if (e >= E) return;
    int d = dst[e];
    int pos = g_rowptr[d] + atomicAdd(&g_cnt2[d], 1);
    g_csr[pos] = src[e];
}

// ---------------- W pre-split: fp32 [k][n] -> fp16 hi/lo uint2 [n][kp] -------
__global__ void k_wsplit(const float* __restrict__ W1,
                         const float* __restrict__ W2) {
    int idx = blockIdx.x * blockDim.x + threadIdx.x;   // 2*128*64
    if (idx >= 2 * DD * 64) return;
    int l  = idx >> 13;
    int r  = idx & 8191;
    int nn = r >> 6;
    int kp = r & 63;
    const float* W = l ? W2 : W1;
    float v0 = W[(size_t)(2 * kp) * DD + nn];
    float v1 = W[(size_t)(2 * kp + 1) * DD + nn];
    __half h0 = __float2half_rn(v0);
    __half h1 = __float2half_rn(v1);
    __half l0 = __float2half_rn(v0 - __half2float(h0));
    __half l1 = __float2half_rn(v1 - __half2float(h1));
    uint32_t hi = ((uint32_t)__half_as_ushort(h1) << 16) | __half_as_ushort(h0);
    uint32_t lo = ((uint32_t)__half_as_ushort(l1) << 16) | __half_as_ushort(l0);
    g_Wsp[idx] = make_uint2(hi, lo);
}

// ---------------- tensor-core GEMM: C[n,128] = A'[n,128] @ W ----------------
// fp16 2-way split, 3-term m16n8k16 HMMA, fp32 accum.
// Block 64 rows x 128 cols, 8 warps (warp tile 16x64). A staged packed in
// smem as uint2 (hi,lo) per k-pair; W read directly from pre-split global.
#define APAD 68
#define SMEM_T (64 * APAD * 8)

__device__ __forceinline__ void mma_f16(float* d, uint32_t a0, uint32_t a1,
                                        uint32_t a2, uint32_t a3,
                                        uint32_t b0, uint32_t b1) {
    asm volatile(
        "mma.sync.aligned.m16n8k16.row.col.f32.f16.f16.f32 "
        "{%0,%1,%2,%3}, {%4,%5,%6,%7}, {%8,%9}, {%0,%1,%2,%3};"
        : "+f"(d[0]), "+f"(d[1]), "+f"(d[2]), "+f"(d[3])
        : "r"(a0), "r"(a1), "r"(a2), "r"(a3), "r"(b0), "r"(b1));
}

__device__ __forceinline__ void pack2(float x, float y, uint32_t& hi,
                                      uint32_t& lo) {
    __half hx = __float2half_rn(x), hy = __float2half_rn(y);
    __half lx = __float2half_rn(x - __half2float(hx));
    __half ly = __float2half_rn(y - __half2float(hy));
    hi = ((uint32_t)__half_as_ushort(hy) << 16) | __half_as_ushort(hx);
    lo = ((uint32_t)__half_as_ushort(ly) << 16) | __half_as_ushort(lx);
}

__global__ void __launch_bounds__(256) k_gemm(const float* __restrict__ A,
                                              const uint2* __restrict__ Wsp,
                                              float* __restrict__ C, int n,
                                              int fuseBN) {
    extern __shared__ uint2 sA[];    // [64][APAD] (hi, lo) per k-pair
    const int tid  = threadIdx.x;
    const int lane = tid & 31;
    const int w    = tid >> 5;
    const int g    = lane >> 2;
    const int t    = lane & 3;
    const int row0 = blockIdx.x * 64;
    const int rowb = (w & 3) * 16;
    const int colb = (w >> 2) * 64;

    // ---- stage A tile [64 rows][128 k] split fp16 hi/lo ----
    const float4* A4 = (const float4*)A;
#pragma unroll
    for (int i = 0; i < 8; i++) {
        int idx = tid + i * 256;          // 2048 float4
        int r = idx >> 5, c = idx & 31;   // c = float4 index (= 2 k-pairs)
        int gr = row0 + r;
        float4 v = (gr < n) ? A4[(size_t)gr * 32 + c]
                            : make_float4(0.f, 0.f, 0.f, 0.f);
        if (fuseBN) {
            float4 sa = ((const float4*)g_sA)[c];
            float4 sb = ((const float4*)g_sB)[c];
            v.x = fmaxf(fmaf(v.x, sa.x, sb.x), 0.f);
            v.y = fmaxf(fmaf(v.y, sa.y, sb.y), 0.f);
            v.z = fmaxf(fmaf(v.z, sa.z, sb.z), 0.f);
            v.w = fmaxf(fmaf(v.w, sa.w, sb.w), 0.f);
        }
        uint32_t h0, l0, h1, l1;
        pack2(v.x, v.y, h0, l0);
        pack2(v.z, v.w, h1, l1);
        uint4 pk = make_uint4(h0, l0, h1, l1);
        *(uint4*)&sA[r * APAD + c * 2] = pk;
    }
    __syncthreads();

    float acc[8][4];
#pragma unroll
    for (int nt = 0; nt < 8; nt++)
#pragma unroll
        for (int q = 0; q < 4; q++) acc[nt][q] = 0.f;

#pragma unroll
    for (int kf = 0; kf < 8; kf++) {
        uint2 a0 = sA[(rowb + g) * APAD + kf * 8 + t];
        uint2 a1 = sA[(rowb + g + 8) * APAD + kf * 8 + t];
        uint2 a2 = sA[(rowb + g) * APAD + kf * 8 + t + 4];
        uint2 a3 = sA[(rowb + g + 8) * APAD + kf * 8 + t + 4];
#pragma unroll
        for (int nt = 0; nt < 8; nt++) {
            const uint2* bp = Wsp + (size_t)(colb + nt * 8 + g) * 64 + kf * 8 + t;
            uint2 b0 = bp[0];
            uint2 b1 = bp[4];
            mma_f16(acc[nt], a0.x, a1.x, a2.x, a3.x, b0.x, b1.x);  // hh
            mma_f16(acc[nt], a0.x, a1.x, a2.x, a3.x, b0.y, b1.y);  // hl
            mma_f16(acc[nt], a0.y, a1.y, a2.y, a3.y, b0.x, b1.x);  // lh
        }
    }

    int r0 = row0 + rowb + g;
    int r1 = r0 + 8;
#pragma unroll
    for (int nt = 0; nt < 8; nt++) {
        int cc = colb + nt * 8 + t * 2;
        if (r0 < n) *(float2*)&C[(size_t)r0 * DD + cc] =
            make_float2(acc[nt][0], acc[nt][1]);
        if (r1 < n) *(float2*)&C[(size_t)r1 * DD + cc] =
            make_float2(acc[nt][2], acc[nt][3]);
    }
}

// ---------------- CSR gather: one warp per destination node ------------------
__global__ void __launch_bounds__(256) k_gather(const float* __restrict__ hw,
                                                const float* __restrict__ bias,
                                                const float* __restrict__ agg,
                                                float* __restrict__ outbuf,
                                                int n, int skip) {
    int d = (blockIdx.x * blockDim.x + threadIdx.x) >> 5;
    int lane = threadIdx.x & 31;
    if (d >= n) return;

    const float4* hw4 = (const float4*)hw;
    float invd = g_dis[d];
    float sw = invd * invd;

    float4 acc = ((const float4*)bias)[lane];
    float4 hd = hw4[(size_t)d * 32 + lane];
    acc.x = fmaf(hd.x, sw, acc.x);
    acc.y = fmaf(hd.y, sw, acc.y);
    acc.z = fmaf(hd.z, sw, acc.z);
    acc.w = fmaf(hd.w, sw, acc.w);
    if (skip) {
        float4 a  = ((const float4*)agg)[(size_t)d * 32 + lane];
        float4 sa = ((const float4*)g_sA)[lane];
        float4 sb = ((const float4*)g_sB)[lane];
        acc.x += fmaxf(fmaf(a.x, sa.x, sb.x), 0.f);
        acc.y += fmaxf(fmaf(a.y, sa.y, sb.y), 0.f);
        acc.z += fmaxf(fmaf(a.z, sa.z, sb.z), 0.f);
        acc.w += fmaxf(fmaf(a.w, sa.w, sb.w), 0.f);
    }

    int j   = g_rowptr[d];
    int end = g_rowptr[d + 1];
    for (; j + 3 < end; j += 4) {
        int s0 = g_csr[j],     s1 = g_csr[j + 1];
        int s2 = g_csr[j + 2], s3 = g_csr[j + 3];
        float w0 = g_dis[s0] * invd, w1 = g_dis[s1] * invd;
        float w2 = g_dis[s2] * invd, w3 = g_dis[s3] * invd;
        float4 v0 = hw4[(size_t)s0 * 32 + lane];
        float4 v1 = hw4[(size_t)s1 * 32 + lane];
        float4 v2 = hw4[(size_t)s2 * 32 + lane];
        float4 v3 = hw4[(size_t)s3 * 32 + lane];
        acc.x = fmaf(v0.x, w0, fmaf(v1.x, w1, fmaf(v2.x, w2, fmaf(v3.x, w3, acc.x))));
        acc.y = fmaf(v0.y, w0, fmaf(v1.y, w1, fmaf(v2.y, w2, fmaf(v3.y, w3, acc.y))));
        acc.z = fmaf(v0.z, w0, fmaf(v1.z, w1, fmaf(v2.z, w2, fmaf(v3.z, w3, acc.z))));
        acc.w = fmaf(v0.w, w0, fmaf(v1.w, w1, fmaf(v2.w, w2, fmaf(v3.w, w3, acc.w))));
    }
    for (; j < end; ++j) {
        int s = g_csr[j];
        float w = g_dis[s] * invd;
        float4 v = hw4[(size_t)s * 32 + lane];
        acc.x = fmaf(v.x, w, acc.x);
        acc.y = fmaf(v.y, w, acc.y);
        acc.z = fmaf(v.z, w, acc.z);
        acc.w = fmaf(v.w, w, acc.w);
    }
    ((float4*)outbuf)[(size_t)d * 32 + lane] = acc;
}

// ---------------- BN column stats ---------------------------------------------
__global__ void k_bnstats(const float* __restrict__ agg, int n) {
    int c = threadIdx.x;
    float s = 0.f, sq = 0.f;
    for (int r = blockIdx.x; r < n; r += gridDim.x) {
        float v = agg[(size_t)r * DD + c];
        s += v;
        sq = fmaf(v, v, sq);
    }
    atomicAdd(&g_bn[c], s);
    atomicAdd(&g_bn[DD + c], sq);
}

__global__ void k_bnfinal(const float* __restrict__ gamma,
                          const float* __restrict__ beta, float inv_n) {
    int c = threadIdx.x;
    float mu = g_bn[c] * inv_n;
    float var = g_bn[DD + c] * inv_n - mu * mu;
    float rstd = rsqrtf(var + 1e-5f);
    float a = gamma[c] * rstd;
    g_sA[c] = a;
    g_sB[c] = beta[c] - mu * a;
}

// ============================================================================
extern "C" void kernel_launch(void* const* d_in, const int* in_sizes, int n_in,
                              void* d_out, int out_size) {
    const float* x     = (const float*)d_in[0];
    const int*   ei    = (const int*)d_in[1];
    const float* W1    = (const float*)d_in[2];
    const float* b1    = (const float*)d_in[3];
    const float* W2    = (const float*)d_in[4];
    const float* b2    = (const float*)d_in[5];
    const float* gamma = (const float*)d_in[6];
    const float* beta  = (const float*)d_in[7];
    float*       out   = (float*)d_out;

    const int n = in_sizes[0] / DD;
    const int E = in_sizes[1] / 2;
    const int* src = ei;
    const int* dst = ei + E;

    static int inited = 0;
    static cudaStream_t s2;
    static cudaEvent_t evFork, evJoin;
    static void *p_cnt, *p_cnt2, *p_bn, *p_hw, *p_agg, *p_wsp;
    if (!inited) {
        cudaFuncSetAttribute(k_gemm, cudaFuncAttributeMaxDynamicSharedMemorySize,
                             SMEM_T);
        cudaStreamCreateWithFlags(&s2, cudaStreamNonBlocking);
        cudaEventCreateWithFlags(&evFork, cudaEventDisableTiming);
        cudaEventCreateWithFlags(&evJoin, cudaEventDisableTiming);
        cudaGetSymbolAddress(&p_cnt,  g_cnt);
        cudaGetSymbolAddress(&p_cnt2, g_cnt2);
        cudaGetSymbolAddress(&p_bn,   g_bn);
        cudaGetSymbolAddress(&p_hw,   g_hw);
        cudaGetSymbolAddress(&p_agg,  g_agg);
        cudaGetSymbolAddress(&p_wsp,  g_Wsp);
        inited = 1;
    }
    float* hw  = (float*)p_hw;
    float* agg = (float*)p_agg;
    const uint2* wsp = (const uint2*)p_wsp;

    const int TB = 256;
    const int n_grid    = (n + TB - 1) / TB;
    const int e_grid    = (E + TB - 1) / TB;
    const int gemm_grid = (n + 63) / 64;
    const int gat_grid  = (n * 32 + TB - 1) / TB;

    // ---- fork: CSR build on s2, overlapped with wsplit+GEMM1 ----
    cudaEventRecord(evFork, 0);
    cudaStreamWaitEvent(s2, evFork, 0);
    cudaMemsetAsync(p_cnt,  0, (size_t)n * 4, s2);
    cudaMemsetAsync(p_cnt2, 0, (size_t)n * 4, s2);
    cudaMemsetAsync(p_bn,   0, 2 * DD * 4, s2);
    k_deg  <<<e_grid, TB, 0, s2>>>(dst, E);
    k_scan1<<<n_grid, TB, 0, s2>>>(n);
    k_scan2<<<1,      TB, 0, s2>>>(n_grid, n);
    k_scan3<<<n_grid, TB, 0, s2>>>(n);
    k_fill <<<e_grid, TB, 0, s2>>>(src, dst, E);
    cudaEventRecord(evJoin, s2);

    // ---- layer 1 (main stream) ----
    k_wsplit<<<(2 * DD * 64 + TB - 1) / TB, TB>>>(W1, W2);
    k_gemm<<<gemm_grid, TB, SMEM_T>>>(x, wsp, hw, n, 0);
    cudaStreamWaitEvent(0, evJoin, 0);
    k_gather<<<gat_grid, TB>>>(hw, b1, nullptr, agg, n, 0);
    k_bnstats<<<512, DD>>>(agg, n);
    k_bnfinal<<<1, DD>>>(gamma, beta, 1.0f / (float)n);

    // ---- layer 2 ----
    k_gemm<<<gemm_grid, TB, SMEM_T>>>(agg, wsp + DD * 64, hw, n, 1);
    k_gather<<<gat_grid, TB>>>(hw, b2, agg, out, n, 1);
}

// round 9
// speedup vs baseline: 1.3641x; 1.0086x over previous
#include <cuda_runtime.h>
#include <cuda_fp16.h>
#include <stdint.h>

#define DD 128
#define NMAX 50176
#define EMAX 819200

// ---------------- scratch (static device globals; no allocation) ------------
__device__ int    g_cnt   [NMAX];
__device__ int    g_cnt2  [NMAX];
__device__ int    g_rowptr[NMAX + 1];
__device__ int    g_csr   [EMAX];
__device__ int    g_bsum  [256];
__device__ int    g_boff  [256];
__device__ float  g_dis   [NMAX];
__device__ float  g_hw    [NMAX * DD];      // fp32 GEMM output
__device__ __half g_hw16  [NMAX * DD];      // fp16 shadow (gather edges)
__device__ float  g_agg   [NMAX * DD];
__device__ float  g_bn    [2 * DD];
__device__ float  g_sA    [DD];
__device__ float  g_sB    [DD];
__device__ uint2  g_Wsp   [2 * DD * 64];    // [layer][n][kp] fp16x2 (hi, lo)

// ---------------- in-degree histogram over dst -------------------------------
__global__ void k_deg(const int* __restrict__ dst, int E) {
    int e = blockIdx.x * blockDim.x + threadIdx.x;
    if (e < E) atomicAdd(&g_cnt[dst[e]], 1);
}

// ---------------- scan phase 1: exclusive block scan + block sum + dis -------
__global__ void __launch_bounds__(256) k_scan1(int n) {
    __shared__ int s[256];
    int t = threadIdx.x;
    int i = blockIdx.x * 256 + t;
    int v = (i < n) ? g_cnt[i] : 0;
    if (i < n) g_dis[i] = rsqrtf((float)(1 + v));
    s[t] = v;
    __syncthreads();
#pragma unroll
    for (int off = 1; off < 256; off <<= 1) {
        int u = (t >= off) ? s[t - off] : 0;
        __syncthreads();
        s[t] += u;
        __syncthreads();
    }
    if (i <= n) g_rowptr[i] = s[t] - v;
    if (t == 255) g_bsum[blockIdx.x] = s[255];
}

__global__ void __launch_bounds__(256) k_scan2(int nb, int n) {
    __shared__ int s[256];
    int t = threadIdx.x;
    int v = (t < nb) ? g_bsum[t] : 0;
    s[t] = v;
    __syncthreads();
#pragma unroll
    for (int off = 1; off < 256; off <<= 1) {
        int u = (t >= off) ? s[t - off] : 0;
        __syncthreads();
        s[t] += u;
        __syncthreads();
    }
    if (t < nb) g_boff[t] = s[t] - v;
    if (t == 255) g_rowptr[n] = s[255];
}

__global__ void __launch_bounds__(256) k_scan3(int n) {
    int i = blockIdx.x * 256 + threadIdx.x;
    if (i < n) g_rowptr[i] += g_boff[blockIdx.x];
}

__global__ void k_fill(const int* __restrict__ src,
                       const int* __restrict__ dst, int E) {
    int e = blockIdx.x * blockDim.x + threadIdx.x;
    if (e >= E) return;
    int d = dst[e];
    int pos = g_rowptr[d] + atomicAdd(&g_cnt2[d], 1);
    g_csr[pos] = src[e];
}

// ---------------- W pre-split: fp32 [k][n] -> fp16 hi/lo uint2 [n][kp] -------
__global__ void k_wsplit(const float* __restrict__ W1,
                         const float* __restrict__ W2) {
    int idx = blockIdx.x * blockDim.x + threadIdx.x;   // 2*128*64
    if (idx >= 2 * DD * 64) return;
    int l  = idx >> 13;
    int r  = idx & 8191;
    int nn = r >> 6;
    int kp = r & 63;
    const float* W = l ? W2 : W1;
    float v0 = W[(size_t)(2 * kp) * DD + nn];
    float v1 = W[(size_t)(2 * kp + 1) * DD + nn];
    __half h0 = __float2half_rn(v0);
    __half h1 = __float2half_rn(v1);
    __half l0 = __float2half_rn(v0 - __half2float(h0));
    __half l1 = __float2half_rn(v1 - __half2float(h1));
    uint32_t hi = ((uint32_t)__half_as_ushort(h1) << 16) | __half_as_ushort(h0);
    uint32_t lo = ((uint32_t)__half_as_ushort(l1) << 16) | __half_as_ushort(l0);
    g_Wsp[idx] = make_uint2(hi, lo);
}

// ---------------- tensor-core GEMM: C = A' @ W  (+ fp16 shadow write) --------
#define APAD 68
#define SMEM_T (64 * APAD * 8)

__device__ __forceinline__ void mma_f16(float* d, uint32_t a0, uint32_t a1,
                                        uint32_t a2, uint32_t a3,
                                        uint32_t b0, uint32_t b1) {
    asm volatile(
        "mma.sync.aligned.m16n8k16.row.col.f32.f16.f16.f32 "
        "{%0,%1,%2,%3}, {%4,%5,%6,%7}, {%8,%9}, {%0,%1,%2,%3};"
        : "+f"(d[0]), "+f"(d[1]), "+f"(d[2]), "+f"(d[3])
        : "r"(a0), "r"(a1), "r"(a2), "r"(a3), "r"(b0), "r"(b1));
}

__device__ __forceinline__ void pack2(float x, float y, uint32_t& hi,
                                      uint32_t& lo) {
    __half hx = __float2half_rn(x), hy = __float2half_rn(y);
    __half lx = __float2half_rn(x - __half2float(hx));
    __half ly = __float2half_rn(y - __half2float(hy));
    hi = ((uint32_t)__half_as_ushort(hy) << 16) | __half_as_ushort(hx);
    lo = ((uint32_t)__half_as_ushort(ly) << 16) | __half_as_ushort(lx);
}

__global__ void __launch_bounds__(256) k_gemm(const float* __restrict__ A,
                                              const uint2* __restrict__ Wsp,
                                              float* __restrict__ C,
                                              __half* __restrict__ C16,
                                              int n, int fuseBN) {
    extern __shared__ uint2 sA[];    // [64][APAD] (hi, lo) per k-pair
    const int tid  = threadIdx.x;
    const int lane = tid & 31;
    const int w    = tid >> 5;
    const int g    = lane >> 2;
    const int t    = lane & 3;
    const int row0 = blockIdx.x * 64;
    const int rowb = (w & 3) * 16;
    const int colb = (w >> 2) * 64;

    const float4* A4 = (const float4*)A;
#pragma unroll
    for (int i = 0; i < 8; i++) {
        int idx = tid + i * 256;
        int r = idx >> 5, c = idx & 31;
        int gr = row0 + r;
        float4 v = (gr < n) ? A4[(size_t)gr * 32 + c]
                            : make_float4(0.f, 0.f, 0.f, 0.f);
        if (fuseBN) {
            float4 sa = ((const float4*)g_sA)[c];
            float4 sb = ((const float4*)g_sB)[c];
            v.x = fmaxf(fmaf(v.x, sa.x, sb.x), 0.f);
            v.y = fmaxf(fmaf(v.y, sa.y, sb.y), 0.f);
            v.z = fmaxf(fmaf(v.z, sa.z, sb.z), 0.f);
            v.w = fmaxf(fmaf(v.w, sa.w, sb.w), 0.f);
        }
        uint32_t h0, l0, h1, l1;
        pack2(v.x, v.y, h0, l0);
        pack2(v.z, v.w, h1, l1);
        *(uint4*)&sA[r * APAD + c * 2] = make_uint4(h0, l0, h1, l1);
    }
    __syncthreads();

    float acc[8][4];
#pragma unroll
    for (int nt = 0; nt < 8; nt++)
#pragma unroll
        for (int q = 0; q < 4; q++) acc[nt][q] = 0.f;

#pragma unroll
    for (int kf = 0; kf < 8; kf++) {
        uint2 a0 = sA[(rowb + g) * APAD + kf * 8 + t];
        uint2 a1 = sA[(rowb + g + 8) * APAD + kf * 8 + t];
        uint2 a2 = sA[(rowb + g) * APAD + kf * 8 + t + 4];
        uint2 a3 = sA[(rowb + g + 8) * APAD + kf * 8 + t + 4];
#pragma unroll
        for (int nt = 0; nt < 8; nt++) {
            const uint2* bp = Wsp + (size_t)(colb + nt * 8 + g) * 64 + kf * 8 + t;
            uint2 b0 = bp[0];
            uint2 b1 = bp[4];
            mma_f16(acc[nt], a0.x, a1.x, a2.x, a3.x, b0.x, b1.x);  // hh
            mma_f16(acc[nt], a0.x, a1.x, a2.x, a3.x, b0.y, b1.y);  // hl
            mma_f16(acc[nt], a0.y, a1.y, a2.y, a3.y, b0.x, b1.x);  // lh
        }
    }

    int r0 = row0 + rowb + g;
    int r1 = r0 + 8;
#pragma unroll
    for (int nt = 0; nt < 8; nt++) {
        int cc = colb + nt * 8 + t * 2;
        if (r0 < n) {
            *(float2*)&C[(size_t)r0 * DD + cc] = make_float2(acc[nt][0], acc[nt][1]);
            __half2 hv = __floats2half2_rn(acc[nt][0], acc[nt][1]);
            *(__half2*)&C16[(size_t)r0 * DD + cc] = hv;
        }
        if (r1 < n) {
            *(float2*)&C[(size_t)r1 * DD + cc] = make_float2(acc[nt][2], acc[nt][3]);
            __half2 hv = __floats2half2_rn(acc[nt][2], acc[nt][3]);
            *(__half2*)&C16[(size_t)r1 * DD + cc] = hv;
        }
    }
}

// ---------------- CSR gather: warp per dst node; edges from fp16 shadow ------
__global__ void __launch_bounds__(256) k_gather(const float* __restrict__ hw,
                                                const __half* __restrict__ hw16,
                                                const float* __restrict__ bias,
                                                const float* __restrict__ agg,
                                                float* __restrict__ outbuf,
                                                int n, int skip) {
    int d = (blockIdx.x * blockDim.x + threadIdx.x) >> 5;
    int lane = threadIdx.x & 31;
    if (d >= n) return;

    float invd = g_dis[d];
    float sw = invd * invd;

    // self-loop + bias in full fp32
    float4 acc = ((const float4*)bias)[lane];
    float4 hd = ((const float4*)hw)[(size_t)d * 32 + lane];
    acc.x = fmaf(hd.x, sw, acc.x);
    acc.y = fmaf(hd.y, sw, acc.y);
    acc.z = fmaf(hd.z, sw, acc.z);
    acc.w = fmaf(hd.w, sw, acc.w);
    if (skip) {
        float4 a  = ((const float4*)agg)[(size_t)d * 32 + lane];
        float4 sa = ((const float4*)g_sA)[lane];
        float4 sb = ((const float4*)g_sB)[lane];
        acc.x += fmaxf(fmaf(a.x, sa.x, sb.x), 0.f);
        acc.y += fmaxf(fmaf(a.y, sa.y, sb.y), 0.f);
        acc.z += fmaxf(fmaf(a.z, sa.z, sb.z), 0.f);
        acc.w += fmaxf(fmaf(a.w, sa.w, sb.w), 0.f);
    }

    // edge gather from fp16 shadow: lane owns 4 cols = 2 half2 = one uint2
    const uint2* hw2 = (const uint2*)hw16;   // 32 uint2 per row
    int j   = g_rowptr[d];
    int end = g_rowptr[d + 1];
    for (; j + 3 < end; j += 4) {
        int s0 = g_csr[j],     s1 = g_csr[j + 1];
        int s2 = g_csr[j + 2], s3 = g_csr[j + 3];
        float w0 = g_dis[s0] * invd, w1 = g_dis[s1] * invd;
        float w2 = g_dis[s2] * invd, w3 = g_dis[s3] * invd;
        uint2 u0 = hw2[(size_t)s0 * 32 + lane];
        uint2 u1 = hw2[(size_t)s1 * 32 + lane];
        uint2 u2 = hw2[(size_t)s2 * 32 + lane];
        uint2 u3 = hw2[(size_t)s3 * 32 + lane];
        float2 p0 = __half22float2(*(__half2*)&u0.x), q0 = __half22float2(*(__half2*)&u0.y);
        float2 p1 = __half22float2(*(__half2*)&u1.x), q1 = __half22float2(*(__half2*)&u1.y);
        float2 p2 = __half22float2(*(__half2*)&u2.x), q2 = __half22float2(*(__half2*)&u2.y);
        float2 p3 = __half22float2(*(__half2*)&u3.x), q3 = __half22float2(*(__half2*)&u3.y);
        acc.x = fmaf(p0.x, w0, fmaf(p1.x, w1, fmaf(p2.x, w2, fmaf(p3.x, w3, acc.x))));
        acc.y = fmaf(p0.y, w0, fmaf(p1.y, w1, fmaf(p2.y, w2, fmaf(p3.y, w3, acc.y))));
        acc.z = fmaf(q0.x, w0, fmaf(q1.x, w1, fmaf(q2.x, w2, fmaf(q3.x, w3, acc.z))));
        acc.w = fmaf(q0.y, w0, fmaf(q1.y, w1, fmaf(q2.y, w2, fmaf(q3.y, w3, acc.w))));
    }
    for (; j < end; ++j) {
        int s = g_csr[j];
        float w = g_dis[s] * invd;
        uint2 u = hw2[(size_t)s * 32 + lane];
        float2 p = __half22float2(*(__half2*)&u.x);
        float2 q = __half22float2(*(__half2*)&u.y);
        acc.x = fmaf(p.x, w, acc.x);
        acc.y = fmaf(p.y, w, acc.y);
        acc.z = fmaf(q.x, w, acc.z);
        acc.w = fmaf(q.y, w, acc.w);
    }
    ((float4*)outbuf)[(size_t)d * 32 + lane] = acc;
}

// ---------------- BN column stats ---------------------------------------------
__global__ void k_bnstats(const float* __restrict__ agg, int n) {
    int c = threadIdx.x;
    float s = 0.f, sq = 0.f;
    for (int r = blockIdx.x; r < n; r += gridDim.x) {
        float v = agg[(size_t)r * DD + c];
        s += v;
        sq = fmaf(v, v, sq);
    }
    atomicAdd(&g_bn[c], s);
    atomicAdd(&g_bn[DD + c], sq);
}

__global__ void k_bnfinal(const float* __restrict__ gamma,
                          const float* __restrict__ beta, float inv_n) {
    int c = threadIdx.x;
    float mu = g_bn[c] * inv_n;
    float var = g_bn[DD + c] * inv_n - mu * mu;
    float rstd = rsqrtf(var + 1e-5f);
    float a = gamma[c] * rstd;
    g_sA[c] = a;
    g_sB[c] = beta[c] - mu * a;
}

// ============================================================================
extern "C" void kernel_launch(void* const* d_in, const int* in_sizes, int n_in,
                              void* d_out, int out_size) {
    const float* x     = (const float*)d_in[0];
    const int*   ei    = (const int*)d_in[1];
    const float* W1    = (const float*)d_in[2];
    const float* b1    = (const float*)d_in[3];
    const float* W2    = (const float*)d_in[4];
    const float* b2    = (const float*)d_in[5];
    const float* gamma = (const float*)d_in[6];
    const float* beta  = (const float*)d_in[7];
    float*       out   = (float*)d_out;

    const int n = in_sizes[0] / DD;
    const int E = in_sizes[1] / 2;
    const int* src = ei;
    const int* dst = ei + E;

    static int inited = 0;
    static cudaStream_t s2;
    static cudaEvent_t evFork, evJoin;
    static void *p_cnt, *p_cnt2, *p_bn, *p_hw, *p_hw16, *p_agg, *p_wsp;
    if (!inited) {
        cudaFuncSetAttribute(k_gemm, cudaFuncAttributeMaxDynamicSharedMemorySize,
                             SMEM_T);
        cudaStreamCreateWithFlags(&s2, cudaStreamNonBlocking);
        cudaEventCreateWithFlags(&evFork, cudaEventDisableTiming);
        cudaEventCreateWithFlags(&evJoin, cudaEventDisableTiming);
        cudaGetSymbolAddress(&p_cnt,  g_cnt);
        cudaGetSymbolAddress(&p_cnt2, g_cnt2);
        cudaGetSymbolAddress(&p_bn,   g_bn);
        cudaGetSymbolAddress(&p_hw,   g_hw);
        cudaGetSymbolAddress(&p_hw16, g_hw16);
        cudaGetSymbolAddress(&p_agg,  g_agg);
        cudaGetSymbolAddress(&p_wsp,  g_Wsp);
        inited = 1;
    }
    float*  hw   = (float*)p_hw;
    __half* hw16 = (__half*)p_hw16;
    float*  agg  = (float*)p_agg;
    const uint2* wsp = (const uint2*)p_wsp;

    const int TB = 256;
    const int n_grid    = (n + TB - 1) / TB;
    const int e_grid    = (E + TB - 1) / TB;
    const int gemm_grid = (n + 63) / 64;
    const int gat_grid  = (n * 32 + TB - 1) / TB;

    // ---- fork: CSR build on s2, overlapped with wsplit+GEMM1 ----
    cudaEventRecord(evFork, 0);
    cudaStreamWaitEvent(s2, evFork, 0);
    cudaMemsetAsync(p_cnt,  0, (size_t)n * 4, s2);
    cudaMemsetAsync(p_cnt2, 0, (size_t)n * 4, s2);
    cudaMemsetAsync(p_bn,   0, 2 * DD * 4, s2);
    k_deg  <<<e_grid, TB, 0, s2>>>(dst, E);
    k_scan1<<<n_grid, TB, 0, s2>>>(n);
    k_scan2<<<1,      TB, 0, s2>>>(n_grid, n);
    k_scan3<<<n_grid, TB, 0, s2>>>(n);
    k_fill <<<e_grid, TB, 0, s2>>>(src, dst, E);
    cudaEventRecord(evJoin, s2);

    // ---- layer 1 (main stream) ----
    k_wsplit<<<(2 * DD * 64 + TB - 1) / TB, TB>>>(W1, W2);
    k_gemm<<<gemm_grid, TB, SMEM_T>>>(x, wsp, hw, hw16, n, 0);
    cudaStreamWaitEvent(0, evJoin, 0);
    k_gather<<<gat_grid, TB>>>(hw, hw16, b1, nullptr, agg, n, 0);
    k_bnstats<<<512, DD>>>(agg, n);
    k_bnfinal<<<1, DD>>>(gamma, beta, 1.0f / (float)n);

    // ---- layer 2 ----
    k_gemm<<<gemm_grid, TB, SMEM_T>>>(agg, wsp + DD * 64, hw, hw16, n, 1);
    k_gather<<<gat_grid, TB>>>(hw, hw16, b2, agg, out, n, 1);
}

// round 10
// speedup vs baseline: 1.3728x; 1.0064x over previous
#include <cuda_runtime.h>
#include <cuda_fp16.h>
#include <stdint.h>

#define DD 128
#define NMAX 50176
#define EMAX 819200

// ---------------- scratch (static device globals; no allocation) ------------
__device__ int    g_cnt   [NMAX];
__device__ int    g_cnt2  [NMAX];
__device__ int    g_rowptr[NMAX + 1];
__device__ int    g_csr   [EMAX];
__device__ int    g_bsum  [256];
__device__ int    g_boff  [256];
__device__ float  g_dis   [NMAX];
__device__ float  g_hw    [NMAX * DD];      // fp32 GEMM output
__device__ __half g_hw16  [NMAX * DD];      // fp16 shadow (gather edges)
__device__ float  g_agg   [NMAX * DD];
__device__ float  g_bn    [2 * DD];
__device__ float  g_sA    [DD];
__device__ float  g_sB    [DD];
__device__ uint2  g_Wsp   [2 * DD * 64];    // [layer][n][kp] fp16x2 (hi, lo)

// ---------------- in-degree histogram over dst -------------------------------
__global__ void k_deg(const int* __restrict__ dst, int E) {
    int e = blockIdx.x * blockDim.x + threadIdx.x;
    if (e < E) atomicAdd(&g_cnt[dst[e]], 1);
}

// ---------------- scan phase 1: exclusive block scan + block sum + dis -------
__global__ void __launch_bounds__(256) k_scan1(int n) {
    __shared__ int s[256];
    int t = threadIdx.x;
    int i = blockIdx.x * 256 + t;
    int v = (i < n) ? g_cnt[i] : 0;
    if (i < n) g_dis[i] = rsqrtf((float)(1 + v));
    s[t] = v;
    __syncthreads();
#pragma unroll
    for (int off = 1; off < 256; off <<= 1) {
        int u = (t >= off) ? s[t - off] : 0;
        __syncthreads();
        s[t] += u;
        __syncthreads();
    }
    if (i <= n) g_rowptr[i] = s[t] - v;
    if (t == 255) g_bsum[blockIdx.x] = s[255];
}

__global__ void __launch_bounds__(256) k_scan2(int nb, int n) {
    __shared__ int s[256];
    int t = threadIdx.x;
    int v = (t < nb) ? g_bsum[t] : 0;
    s[t] = v;
    __syncthreads();
#pragma unroll
    for (int off = 1; off < 256; off <<= 1) {
        int u = (t >= off) ? s[t - off] : 0;
        __syncthreads();
        s[t] += u;
        __syncthreads();
    }
    if (t < nb) g_boff[t] = s[t] - v;
    if (t == 255) g_rowptr[n] = s[255];
}

__global__ void __launch_bounds__(256) k_scan3(int n) {
    int i = blockIdx.x * 256 + threadIdx.x;
    if (i < n) g_rowptr[i] += g_boff[blockIdx.x];
}

__global__ void k_fill(const int* __restrict__ src,
                       const int* __restrict__ dst, int E) {
    int e = blockIdx.x * blockDim.x + threadIdx.x;
    if (e >= E) return;
    int d = dst[e];
    int pos = g_rowptr[d] + atomicAdd(&g_cnt2[d], 1);
    g_csr[pos] = src[e];
}

// ---------------- W pre-split: fp32 [k][n] -> fp16 hi/lo uint2 [n][kp] -------
__global__ void k_wsplit(const float* __restrict__ W1,
                         const float* __restrict__ W2) {
    int idx = blockIdx.x * blockDim.x + threadIdx.x;   // 2*128*64
    if (idx >= 2 * DD * 64) return;
    int l  = idx >> 13;
    int r  = idx & 8191;
    int nn = r >> 6;
    int kp = r & 63;
    const float* W = l ? W2 : W1;
    float v0 = W[(size_t)(2 * kp) * DD + nn];
    float v1 = W[(size_t)(2 * kp + 1) * DD + nn];
    __half h0 = __float2half_rn(v0);
    __half h1 = __float2half_rn(v1);
    __half l0 = __float2half_rn(v0 - __half2float(h0));
    __half l1 = __float2half_rn(v1 - __half2float(h1));
    uint32_t hi = ((uint32_t)__half_as_ushort(h1) << 16) | __half_as_ushort(h0);
    uint32_t lo = ((uint32_t)__half_as_ushort(l1) << 16) | __half_as_ushort(l0);
    g_Wsp[idx] = make_uint2(hi, lo);
}

// ---------------- tensor-core GEMM: C = A' @ W  (+ fp16 shadow write) --------
#define APAD 68
#define SMEM_T (64 * APAD * 8)

__device__ __forceinline__ void mma_f16(float* d, uint32_t a0, uint32_t a1,
                                        uint32_t a2, uint32_t a3,
                                        uint32_t b0, uint32_t b1) {
    asm volatile(
        "mma.sync.aligned.m16n8k16.row.col.f32.f16.f16.f32 "
        "{%0,%1,%2,%3}, {%4,%5,%6,%7}, {%8,%9}, {%0,%1,%2,%3};"
        : "+f"(d[0]), "+f"(d[1]), "+f"(d[2]), "+f"(d[3])
        : "r"(a0), "r"(a1), "r"(a2), "r"(a3), "r"(b0), "r"(b1));
}

__device__ __forceinline__ void pack2(float x, float y, uint32_t& hi,
                                      uint32_t& lo) {
    __half hx = __float2half_rn(x), hy = __float2half_rn(y);
    __half lx = __float2half_rn(x - __half2float(hx));
    __half ly = __float2half_rn(y - __half2float(hy));
    hi = ((uint32_t)__half_as_ushort(hy) << 16) | __half_as_ushort(hx);
    lo = ((uint32_t)__half_as_ushort(ly) << 16) | __half_as_ushort(lx);
}

__global__ void __launch_bounds__(256) k_gemm(const float* __restrict__ A,
                                              const uint2* __restrict__ Wsp,
                                              float* __restrict__ C,
                                              __half* __restrict__ C16,
                                              int n, int fuseBN) {
    extern __shared__ uint2 sA[];    // [64][APAD] (hi, lo) per k-pair
    const int tid  = threadIdx.x;
    const int lane = tid & 31;
    const int w    = tid >> 5;
    const int g    = lane >> 2;
    const int t    = lane & 3;
    const int row0 = blockIdx.x * 64;
    const int rowb = (w & 3) * 16;
    const int colb = (w >> 2) * 64;

    const float4* A4 = (const float4*)A;
#pragma unroll
    for (int i = 0; i < 8; i++) {
        int idx = tid + i * 256;
        int r = idx >> 5, c = idx & 31;
        int gr = row0 + r;
        float4 v = (gr < n) ? A4[(size_t)gr * 32 + c]
                            : make_float4(0.f, 0.f, 0.f, 0.f);
        if (fuseBN) {
            float4 sa = ((const float4*)g_sA)[c];
            float4 sb = ((const float4*)g_sB)[c];
            v.x = fmaxf(fmaf(v.x, sa.x, sb.x), 0.f);
            v.y = fmaxf(fmaf(v.y, sa.y, sb.y), 0.f);
            v.z = fmaxf(fmaf(v.z, sa.z, sb.z), 0.f);
            v.w = fmaxf(fmaf(v.w, sa.w, sb.w), 0.f);
        }
        uint32_t h0, l0, h1, l1;
        pack2(v.x, v.y, h0, l0);
        pack2(v.z, v.w, h1, l1);
        *(uint4*)&sA[r * APAD + c * 2] = make_uint4(h0, l0, h1, l1);
    }
    __syncthreads();

    float acc[8][4];
#pragma unroll
    for (int nt = 0; nt < 8; nt++)
#pragma unroll
        for (int q = 0; q < 4; q++) acc[nt][q] = 0.f;

#pragma unroll
    for (int kf = 0; kf < 8; kf++) {
        uint2 a0 = sA[(rowb + g) * APAD + kf * 8 + t];
        uint2 a1 = sA[(rowb + g + 8) * APAD + kf * 8 + t];
        uint2 a2 = sA[(rowb + g) * APAD + kf * 8 + t + 4];
        uint2 a3 = sA[(rowb + g + 8) * APAD + kf * 8 + t + 4];
#pragma unroll
        for (int nt = 0; nt < 8; nt++) {
            const uint2* bp = Wsp + (size_t)(colb + nt * 8 + g) * 64 + kf * 8 + t;
            uint2 b0 = bp[0];
            uint2 b1 = bp[4];
            mma_f16(acc[nt], a0.x, a1.x, a2.x, a3.x, b0.x, b1.x);  // hh
            mma_f16(acc[nt], a0.x, a1.x, a2.x, a3.x, b0.y, b1.y);  // hl
            mma_f16(acc[nt], a0.y, a1.y, a2.y, a3.y, b0.x, b1.x);  // lh
        }
    }

    int r0 = row0 + rowb + g;
    int r1 = r0 + 8;
#pragma unroll
    for (int nt = 0; nt < 8; nt++) {
        int cc = colb + nt * 8 + t * 2;
        if (r0 < n) {
            *(float2*)&C[(size_t)r0 * DD + cc] = make_float2(acc[nt][0], acc[nt][1]);
            *(__half2*)&C16[(size_t)r0 * DD + cc] =
                __floats2half2_rn(acc[nt][0], acc[nt][1]);
        }
        if (r1 < n) {
            *(float2*)&C[(size_t)r1 * DD + cc] = make_float2(acc[nt][2], acc[nt][3]);
            *(__half2*)&C16[(size_t)r1 * DD + cc] =
                __floats2half2_rn(acc[nt][2], acc[nt][3]);
        }
    }
}

// ---------------- CSR gather: warp per dst node, 8 rows in flight ------------
__global__ void __launch_bounds__(256) k_gather(const float* __restrict__ hw,
                                                const __half* __restrict__ hw16,
                                                const float* __restrict__ bias,
                                                const float* __restrict__ agg,
                                                float* __restrict__ outbuf,
                                                int n, int skip) {
    int d = (blockIdx.x * blockDim.x + threadIdx.x) >> 5;
    int lane = threadIdx.x & 31;
    if (d >= n) return;

    float invd = g_dis[d];
    float sw = invd * invd;

    // self-loop + bias in full fp32
    float4 acc = ((const float4*)bias)[lane];
    float4 hd = ((const float4*)hw)[(size_t)d * 32 + lane];
    acc.x = fmaf(hd.x, sw, acc.x);
    acc.y = fmaf(hd.y, sw, acc.y);
    acc.z = fmaf(hd.z, sw, acc.z);
    acc.w = fmaf(hd.w, sw, acc.w);
    if (skip) {
        float4 a  = ((const float4*)agg)[(size_t)d * 32 + lane];
        float4 sa = ((const float4*)g_sA)[lane];
        float4 sb = ((const float4*)g_sB)[lane];
        acc.x += fmaxf(fmaf(a.x, sa.x, sb.x), 0.f);
        acc.y += fmaxf(fmaf(a.y, sa.y, sb.y), 0.f);
        acc.z += fmaxf(fmaf(a.z, sa.z, sb.z), 0.f);
        acc.w += fmaxf(fmaf(a.w, sa.w, sb.w), 0.f);
    }

    const uint2* hw2 = (const uint2*)hw16;   // 32 uint2 per row
    int j   = g_rowptr[d];
    int end = g_rowptr[d + 1];

    // 8 rows in flight per round
    for (; j + 7 < end; j += 8) {
        int   si[8];
        float wi[8];
        uint2 ui[8];
#pragma unroll
        for (int q = 0; q < 8; q++) si[q] = g_csr[j + q];
#pragma unroll
        for (int q = 0; q < 8; q++) wi[q] = g_dis[si[q]];
#pragma unroll
        for (int q = 0; q < 8; q++) ui[q] = hw2[(size_t)si[q] * 32 + lane];
#pragma unroll
        for (int q = 0; q < 8; q++) {
            float wq = wi[q] * invd;
            float2 p = __half22float2(*(__half2*)&ui[q].x);
            float2 r = __half22float2(*(__half2*)&ui[q].y);
            acc.x = fmaf(p.x, wq, acc.x);
            acc.y = fmaf(p.y, wq, acc.y);
            acc.z = fmaf(r.x, wq, acc.z);
            acc.w = fmaf(r.y, wq, acc.w);
        }
    }
    if (j + 3 < end) {
        int   si[4];
        float wi[4];
        uint2 ui[4];
#pragma unroll
        for (int q = 0; q < 4; q++) si[q] = g_csr[j + q];
#pragma unroll
        for (int q = 0; q < 4; q++) wi[q] = g_dis[si[q]];
#pragma unroll
        for (int q = 0; q < 4; q++) ui[q] = hw2[(size_t)si[q] * 32 + lane];
#pragma unroll
        for (int q = 0; q < 4; q++) {
            float wq = wi[q] * invd;
            float2 p = __half22float2(*(__half2*)&ui[q].x);
            float2 r = __half22float2(*(__half2*)&ui[q].y);
            acc.x = fmaf(p.x, wq, acc.x);
            acc.y = fmaf(p.y, wq, acc.y);
            acc.z = fmaf(r.x, wq, acc.z);
            acc.w = fmaf(r.y, wq, acc.w);
        }
        j += 4;
    }
    for (; j < end; ++j) {
        int s = g_csr[j];
        float wq = g_dis[s] * invd;
        uint2 u = hw2[(size_t)s * 32 + lane];
        float2 p = __half22float2(*(__half2*)&u.x);
        float2 r = __half22float2(*(__half2*)&u.y);
        acc.x = fmaf(p.x, wq, acc.x);
        acc.y = fmaf(p.y, wq, acc.y);
        acc.z = fmaf(r.x, wq, acc.z);
        acc.w = fmaf(r.y, wq, acc.w);
    }
    ((float4*)outbuf)[(size_t)d * 32 + lane] = acc;
}

// ---------------- BN column stats ---------------------------------------------
__global__ void k_bnstats(const float* __restrict__ agg, int n) {
    int c = threadIdx.x;
    float s = 0.f, sq = 0.f;
    for (int r = blockIdx.x; r < n; r += gridDim.x) {
        float v = agg[(size_t)r * DD + c];
        s += v;
        sq = fmaf(v, v, sq);
    }
    atomicAdd(&g_bn[c], s);
    atomicAdd(&g_bn[DD + c], sq);
}

__global__ void k_bnfinal(const float* __restrict__ gamma,
                          const float* __restrict__ beta, float inv_n) {
    int c = threadIdx.x;
    float mu = g_bn[c] * inv_n;
    float var = g_bn[DD + c] * inv_n - mu * mu;
    float rstd = rsqrtf(var + 1e-5f);
    float a = gamma[c] * rstd;
    g_sA[c] = a;
    g_sB[c] = beta[c] - mu * a;
}

// ============================================================================
extern "C" void kernel_launch(void* const* d_in, const int* in_sizes, int n_in,
                              void* d_out, int out_size) {
    const float* x     = (const float*)d_in[0];
    const int*   ei    = (const int*)d_in[1];
    const float* W1    = (const float*)d_in[2];
    const float* b1    = (const float*)d_in[3];
    const float* W2    = (const float*)d_in[4];
    const float* b2    = (const float*)d_in[5];
    const float* gamma = (const float*)d_in[6];
    const float* beta  = (const float*)d_in[7];
    float*       out   = (float*)d_out;

    const int n = in_sizes[0] / DD;
    const int E = in_sizes[1] / 2;
    const int* src = ei;
    const int* dst = ei + E;

    static int inited = 0;
    static cudaStream_t s2;
    static cudaEvent_t evFork, evJoin;
    static void *p_cnt, *p_cnt2, *p_bn, *p_hw, *p_hw16, *p_agg, *p_wsp;
    if (!inited) {
        cudaFuncSetAttribute(k_gemm, cudaFuncAttributeMaxDynamicSharedMemorySize,
                             SMEM_T);
        cudaStreamCreateWithFlags(&s2, cudaStreamNonBlocking);
        cudaEventCreateWithFlags(&evFork, cudaEventDisableTiming);
        cudaEventCreateWithFlags(&evJoin, cudaEventDisableTiming);
        cudaGetSymbolAddress(&p_cnt,  g_cnt);
        cudaGetSymbolAddress(&p_cnt2, g_cnt2);
        cudaGetSymbolAddress(&p_bn,   g_bn);
        cudaGetSymbolAddress(&p_hw,   g_hw);
        cudaGetSymbolAddress(&p_hw16, g_hw16);
        cudaGetSymbolAddress(&p_agg,  g_agg);
        cudaGetSymbolAddress(&p_wsp,  g_Wsp);
        inited = 1;
    }
    float*  hw   = (float*)p_hw;
    __half* hw16 = (__half*)p_hw16;
    float*  agg  = (float*)p_agg;
    const uint2* wsp = (const uint2*)p_wsp;

    const int TB = 256;
    const int n_grid    = (n + TB - 1) / TB;
    const int e_grid    = (E + TB - 1) / TB;
    const int gemm_grid = (n + 63) / 64;
    const int gat_grid  = (n * 32 + TB - 1) / TB;

    // ---- fork: CSR build on s2, overlapped with wsplit+GEMM1 ----
    cudaEventRecord(evFork, 0);
    cudaStreamWaitEvent(s2, evFork, 0);
    cudaMemsetAsync(p_cnt,  0, (size_t)n * 4, s2);
    cudaMemsetAsync(p_cnt2, 0, (size_t)n * 4, s2);
    cudaMemsetAsync(p_bn,   0, 2 * DD * 4, s2);
    k_deg  <<<e_grid, TB, 0, s2>>>(dst, E);
    k_scan1<<<n_grid, TB, 0, s2>>>(n);
    k_scan2<<<1,      TB, 0, s2>>>(n_grid, n);
    k_scan3<<<n_grid, TB, 0, s2>>>(n);
    k_fill <<<e_grid, TB, 0, s2>>>(src, dst, E);
    cudaEventRecord(evJoin, s2);

    // ---- layer 1 (main stream) ----
    k_wsplit<<<(2 * DD * 64 + TB - 1) / TB, TB>>>(W1, W2);
    k_gemm<<<gemm_grid, TB, SMEM_T>>>(x, wsp, hw, hw16, n, 0);
    cudaStreamWaitEvent(0, evJoin, 0);
    k_gather<<<gat_grid, TB>>>(hw, hw16, b1, nullptr, agg, n, 0);
    k_bnstats<<<512, DD>>>(agg, n);
    k_bnfinal<<<1, DD>>>(gamma, beta, 1.0f / (float)n);

    // ---- layer 2 ----
    k_gemm<<<gemm_grid, TB, SMEM_T>>>(agg, wsp + DD * 64, hw, hw16, n, 1);
    k_gather<<<gat_grid, TB>>>(hw, hw16, b2, agg, out, n, 1);
}

// round 12
// speedup vs baseline: 1.3961x; 1.0170x over previous
#include <cuda_runtime.h>
#include <cuda_fp16.h>
#include <stdint.h>

#define DD 128
#define NMAX 50176
#define EMAX 819200

// ---------------- scratch (static device globals; no allocation) ------------
__device__ int    g_cnt   [NMAX];
__device__ int    g_cnt2  [NMAX];
__device__ int    g_rowptr[NMAX + 1];
__device__ int    g_csr   [EMAX];
__device__ int    g_bsum  [256];
__device__ int    g_boff  [256];
__device__ float  g_dis   [NMAX];
__device__ __half g_hw16  [NMAX * DD];      // fp16 GEMM output (all consumers)
__device__ float  g_agg   [NMAX * DD];
__device__ float  g_bn    [2 * DD];
__device__ float  g_sA    [DD];
__device__ float  g_sB    [DD];
__device__ uint2  g_Wsp   [2 * DD * 64];    // [layer][n][kp] fp16x2 (hi, lo)

// ---------------- in-degree histogram over dst -------------------------------
__global__ void k_deg(const int* __restrict__ dst, int E) {
    int e = blockIdx.x * blockDim.x + threadIdx.x;
    if (e < E) atomicAdd(&g_cnt[dst[e]], 1);
}

// ---------------- scan phase 1: exclusive block scan + block sum + dis -------
__global__ void __launch_bounds__(256) k_scan1(int n) {
    __shared__ int s[256];
    int t = threadIdx.x;
    int i = blockIdx.x * 256 + t;
    int v = (i < n) ? g_cnt[i] : 0;
    if (i < n) g_dis[i] = rsqrtf((float)(1 + v));
    s[t] = v;
    __syncthreads();
#pragma unroll
    for (int off = 1; off < 256; off <<= 1) {
        int u = (t >= off) ? s[t - off] : 0;
        __syncthreads();
        s[t] += u;
        __syncthreads();
    }
    if (i <= n) g_rowptr[i] = s[t] - v;
    if (t == 255) g_bsum[blockIdx.x] = s[255];
}

__global__ void __launch_bounds__(256) k_scan2(int nb, int n) {
    __shared__ int s[256];
    int t = threadIdx.x;
    int v = (t < nb) ? g_bsum[t] : 0;
    s[t] = v;
    __syncthreads();
#pragma unroll
    for (int off = 1; off < 256; off <<= 1) {
        int u = (t >= off) ? s[t - off] : 0;
        __syncthreads();
        s[t] += u;
        __syncthreads();
    }
    if (t < nb) g_boff[t] = s[t] - v;
    if (t == 255) g_rowptr[n] = s[255];
}

__global__ void __launch_bounds__(256) k_scan3(int n) {
    int i = blockIdx.x * 256 + threadIdx.x;
    if (i < n) g_rowptr[i] += g_boff[blockIdx.x];
}

__global__ void k_fill(const int* __restrict__ src,
                       const int* __restrict__ dst, int E) {
    int e = blockIdx.x * blockDim.x + threadIdx.x;
    if (e >= E) return;
    int d = dst[e];
    int pos = g_rowptr[d] + atomicAdd(&g_cnt2[d], 1);
    g_csr[pos] = src[e];
}

// ---------------- W pre-split: fp32 [k][n] -> fp16 hi/lo uint2 [n][kp] -------
__global__ void k_wsplit(const float* __restrict__ W1,
                         const float* __restrict__ W2) {
    int idx = blockIdx.x * blockDim.x + threadIdx.x;   // 2*128*64
    if (idx >= 2 * DD * 64) return;
    int l  = idx >> 13;
    int r  = idx & 8191;
    int nn = r >> 6;
    int kp = r & 63;
    const float* W = l ? W2 : W1;
    float v0 = W[(size_t)(2 * kp) * DD + nn];
    float v1 = W[(size_t)(2 * kp + 1) * DD + nn];
    __half h0 = __float2half_rn(v0);
    __half h1 = __float2half_rn(v1);
    __half l0 = __float2half_rn(v0 - __half2float(h0));
    __half l1 = __float2half_rn(v1 - __half2float(h1));
    uint32_t hi = ((uint32_t)__half_as_ushort(h1) << 16) | __half_as_ushort(h0);
    uint32_t lo = ((uint32_t)__half_as_ushort(l1) << 16) | __half_as_ushort(l0);
    g_Wsp[idx] = make_uint2(hi, lo);
}

// ---------------- tensor-core GEMM: C16 = A' @ W (2-term: Ah*Wh + Ah*Wl) -----
// A row = 128 k = 64 fp16x2 pairs; smem row stride APAD=68 uint32.
#define APAD 68
#define SMEM_T (64 * APAD * 4)

__device__ __forceinline__ void mma_f16(float* d, uint32_t a0, uint32_t a1,
                                        uint32_t a2, uint32_t a3,
                                        uint32_t b0, uint32_t b1) {
    asm volatile(
        "mma.sync.aligned.m16n8k16.row.col.f32.f16.f16.f32 "
        "{%0,%1,%2,%3}, {%4,%5,%6,%7}, {%8,%9}, {%0,%1,%2,%3};"
        : "+f"(d[0]), "+f"(d[1]), "+f"(d[2]), "+f"(d[3])
        : "r"(a0), "r"(a1), "r"(a2), "r"(a3), "r"(b0), "r"(b1));
}

__global__ void __launch_bounds__(256) k_gemm(const float* __restrict__ A,
                                              const uint2* __restrict__ Wsp,
                                              __half* __restrict__ C16,
                                              int n, int fuseBN) {
    extern __shared__ uint32_t sA[];   // [64][APAD] fp16x2 per k-pair (Ah only)
    const int tid  = threadIdx.x;
    const int lane = tid & 31;
    const int w    = tid >> 5;
    const int g    = lane >> 2;
    const int t    = lane & 3;
    const int row0 = blockIdx.x * 64;
    const int rowb = (w & 3) * 16;
    const int colb = (w >> 2) * 64;

    // ---- stage A tile [64 rows][64 k-pairs] fp16 ----
    const float4* A4 = (const float4*)A;
#pragma unroll
    for (int i = 0; i < 8; i++) {
        int idx = tid + i * 256;
        int r = idx >> 5, c = idx & 31;   // c = float4 index = 2 k-pairs
        int gr = row0 + r;
        float4 v = (gr < n) ? A4[(size_t)gr * 32 + c]
                            : make_float4(0.f, 0.f, 0.f, 0.f);
        if (fuseBN) {
            float4 sa = ((const float4*)g_sA)[c];
            float4 sb = ((const float4*)g_sB)[c];
            v.x = fmaxf(fmaf(v.x, sa.x, sb.x), 0.f);
            v.y = fmaxf(fmaf(v.y, sa.y, sb.y), 0.f);
            v.z = fmaxf(fmaf(v.z, sa.z, sb.z), 0.f);
            v.w = fmaxf(fmaf(v.w, sa.w, sb.w), 0.f);
        }
        __half2 h01 = __floats2half2_rn(v.x, v.y);
        __half2 h23 = __floats2half2_rn(v.z, v.w);
        *(uint2*)&sA[r * APAD + c * 2] =
            make_uint2(*(uint32_t*)&h01, *(uint32_t*)&h23);
    }
    __syncthreads();

    float acc[8][4];
#pragma unroll
    for (int nt = 0; nt < 8; nt++)
#pragma unroll
        for (int q = 0; q < 4; q++) acc[nt][q] = 0.f;

    // kf spans 16 k = 8 pairs: a-frag pairs kf*8+t and kf*8+t+4, rows g / g+8
#pragma unroll
    for (int kf = 0; kf < 8; kf++) {
        uint32_t a0 = sA[(rowb + g) * APAD + kf * 8 + t];
        uint32_t a1 = sA[(rowb + g + 8) * APAD + kf * 8 + t];
        uint32_t a2 = sA[(rowb + g) * APAD + kf * 8 + t + 4];
        uint32_t a3 = sA[(rowb + g + 8) * APAD + kf * 8 + t + 4];
#pragma unroll
        for (int nt = 0; nt < 8; nt++) {
            const uint2* bp = Wsp + (size_t)(colb + nt * 8 + g) * 64 + kf * 8 + t;
            uint2 b0 = bp[0];
            uint2 b1 = bp[4];
            mma_f16(acc[nt], a0, a1, a2, a3, b0.x, b1.x);  // Ah*Wh
            mma_f16(acc[nt], a0, a1, a2, a3, b0.y, b1.y);  // Ah*Wl
        }
    }

    int r0 = row0 + rowb + g;
    int r1 = r0 + 8;
#pragma unroll
    for (int nt = 0; nt < 8; nt++) {
        int cc = colb + nt * 8 + t * 2;
        if (r0 < n) *(__half2*)&C16[(size_t)r0 * DD + cc] =
            __floats2half2_rn(acc[nt][0], acc[nt][1]);
        if (r1 < n) *(__half2*)&C16[(size_t)r1 * DD + cc] =
            __floats2half2_rn(acc[nt][2], acc[nt][3]);
    }
}

// ---------------- CSR gather: warp per dst node, fp16 rows -------------------
__global__ void __launch_bounds__(256) k_gather(const __half* __restrict__ hw16,
                                                const float* __restrict__ bias,
                                                const float* __restrict__ agg,
                                                float* __restrict__ outbuf,
                                                int n, int skip) {
    int d = (blockIdx.x * blockDim.x + threadIdx.x) >> 5;
    int lane = threadIdx.x & 31;
    if (d >= n) return;

    float invd = g_dis[d];
    float sw = invd * invd;
    const uint2* hw2 = (const uint2*)hw16;   // 32 uint2 per row

    float4 acc = ((const float4*)bias)[lane];
    {
        uint2 u = hw2[(size_t)d * 32 + lane];
        float2 p = __half22float2(*(__half2*)&u.x);
        float2 r = __half22float2(*(__half2*)&u.y);
        acc.x = fmaf(p.x, sw, acc.x);
        acc.y = fmaf(p.y, sw, acc.y);
        acc.z = fmaf(r.x, sw, acc.z);
        acc.w = fmaf(r.y, sw, acc.w);
    }
    if (skip) {
        float4 a  = ((const float4*)agg)[(size_t)d * 32 + lane];
        float4 sa = ((const float4*)g_sA)[lane];
        float4 sb = ((const float4*)g_sB)[lane];
        acc.x += fmaxf(fmaf(a.x, sa.x, sb.x), 0.f);
        acc.y += fmaxf(fmaf(a.y, sa.y, sb.y), 0.f);
        acc.z += fmaxf(fmaf(a.z, sa.z, sb.z), 0.f);
        acc.w += fmaxf(fmaf(a.w, sa.w, sb.w), 0.f);
    }

    int j   = g_rowptr[d];
    int end = g_rowptr[d + 1];
    for (; j + 7 < end; j += 8) {
        int   si[8];
        float wi[8];
        uint2 ui[8];
#pragma unroll
        for (int q = 0; q < 8; q++) si[q] = g_csr[j + q];
#pragma unroll
        for (int q = 0; q < 8; q++) wi[q] = g_dis[si[q]];
#pragma unroll
        for (int q = 0; q < 8; q++) ui[q] = hw2[(size_t)si[q] * 32 + lane];
#pragma unroll
        for (int q = 0; q < 8; q++) {
            float wq = wi[q] * invd;
            float2 p = __half22float2(*(__half2*)&ui[q].x);
            float2 r = __half22float2(*(__half2*)&ui[q].y);
            acc.x = fmaf(p.x, wq, acc.x);
            acc.y = fmaf(p.y, wq, acc.y);
            acc.z = fmaf(r.x, wq, acc.z);
            acc.w = fmaf(r.y, wq, acc.w);
        }
    }
    if (j + 3 < end) {
        int   si[4];
        float wi[4];
        uint2 ui[4];
#pragma unroll
        for (int q = 0; q < 4; q++) si[q] = g_csr[j + q];
#pragma unroll
        for (int q = 0; q < 4; q++) wi[q] = g_dis[si[q]];
#pragma unroll
        for (int q = 0; q < 4; q++) ui[q] = hw2[(size_t)si[q] * 32 + lane];
#pragma unroll
        for (int q = 0; q < 4; q++) {
            float wq = wi[q] * invd;
            float2 p = __half22float2(*(__half2*)&ui[q].x);
            float2 r = __half22float2(*(__half2*)&ui[q].y);
            acc.x = fmaf(p.x, wq, acc.x);
            acc.y = fmaf(p.y, wq, acc.y);
            acc.z = fmaf(r.x, wq, acc.z);
            acc.w = fmaf(r.y, wq, acc.w);
        }
        j += 4;
    }
    for (; j < end; ++j) {
        int s = g_csr[j];
        float wq = g_dis[s] * invd;
        uint2 u = hw2[(size_t)s * 32 + lane];
        float2 p = __half22float2(*(__half2*)&u.x);
        float2 r = __half22float2(*(__half2*)&u.y);
        acc.x = fmaf(p.x, wq, acc.x);
        acc.y = fmaf(p.y, wq, acc.y);
        acc.z = fmaf(r.x, wq, acc.z);
        acc.w = fmaf(r.y, wq, acc.w);
    }
    ((float4*)outbuf)[(size_t)d * 32 + lane] = acc;
}

// ---------------- BN column stats ---------------------------------------------
__global__ void k_bnstats(const float* __restrict__ agg, int n) {
    int c = threadIdx.x;
    float s = 0.f, sq = 0.f;
    for (int r = blockIdx.x; r < n; r += gridDim.x) {
        float v = agg[(size_t)r * DD + c];
        s += v;
        sq = fmaf(v, v, sq);
    }
    atomicAdd(&g_bn[c], s);
    atomicAdd(&g_bn[DD + c], sq);
}

__global__ void k_bnfinal(const float* __restrict__ gamma,
                          const float* __restrict__ beta, float inv_n) {
    int c = threadIdx.x;
    float mu = g_bn[c] * inv_n;
    float var = g_bn[DD + c] * inv_n - mu * mu;
    float rstd = rsqrtf(var + 1e-5f);
    float a = gamma[c] * rstd;
    g_sA[c] = a;
    g_sB[c] = beta[c] - mu * a;
}

// ============================================================================
extern "C" void kernel_launch(void* const* d_in, const int* in_sizes, int n_in,
                              void* d_out, int out_size) {
    const float* x     = (const float*)d_in[0];
    const int*   ei    = (const int*)d_in[1];
    const float* W1    = (const float*)d_in[2];
    const float* b1    = (const float*)d_in[3];
    const float* W2    = (const float*)d_in[4];
    const float* b2    = (const float*)d_in[5];
    const float* gamma = (const float*)d_in[6];
    const float* beta  = (const float*)d_in[7];
    float*       out   = (float*)d_out;

    const int n = in_sizes[0] / DD;
    const int E = in_sizes[1] / 2;
    const int* src = ei;
    const int* dst = ei + E;

    static int inited = 0;
    static cudaStream_t s2;
    static cudaEvent_t evFork, evJoin;
    static void *p_cnt, *p_cnt2, *p_bn, *p_hw16, *p_agg, *p_wsp;
    if (!inited) {
        cudaFuncSetAttribute(k_gemm, cudaFuncAttributeMaxDynamicSharedMemorySize,
                             SMEM_T);
        cudaStreamCreateWithFlags(&s2, cudaStreamNonBlocking);
        cudaEventCreateWithFlags(&evFork, cudaEventDisableTiming);
        cudaEventCreateWithFlags(&evJoin, cudaEventDisableTiming);
        cudaGetSymbolAddress(&p_cnt,  g_cnt);
        cudaGetSymbolAddress(&p_cnt2, g_cnt2);
        cudaGetSymbolAddress(&p_bn,   g_bn);
        cudaGetSymbolAddress(&p_hw16, g_hw16);
        cudaGetSymbolAddress(&p_agg,  g_agg);
        cudaGetSymbolAddress(&p_wsp,  g_Wsp);
        inited = 1;
    }
    __half* hw16 = (__half*)p_hw16;
    float*  agg  = (float*)p_agg;
    const uint2* wsp = (const uint2*)p_wsp;

    const int TB = 256;
    const int n_grid    = (n + TB - 1) / TB;
    const int e_grid    = (E + TB - 1) / TB;
    const int gemm_grid = (n + 63) / 64;
    const int gat_grid  = (n * 32 + TB - 1) / TB;

    // ---- fork: CSR build on s2, overlapped with wsplit+GEMM1 ----
    cudaEventRecord(evFork, 0);
    cudaStreamWaitEvent(s2, evFork, 0);
    cudaMemsetAsync(p_cnt,  0, (size_t)n * 4, s2);
    cudaMemsetAsync(p_cnt2, 0, (size_t)n * 4, s2);
    cudaMemsetAsync(p_bn,   0, 2 * DD * 4, s2);
    k_deg  <<<e_grid, TB, 0, s2>>>(dst, E);
    k_scan1<<<n_grid, TB, 0, s2>>>(n);
    k_scan2<<<1,      TB, 0, s2>>>(n_grid, n);
    k_scan3<<<n_grid, TB, 0, s2>>>(n);
    k_fill <<<e_grid, TB, 0, s2>>>(src, dst, E);
    cudaEventRecord(evJoin, s2);

    // ---- layer 1 (main stream) ----
    k_wsplit<<<(2 * DD * 64 + TB - 1) / TB, TB>>>(W1, W2);
    k_gemm<<<gemm_grid, TB, SMEM_T>>>(x, wsp, hw16, n, 0);
    cudaStreamWaitEvent(0, evJoin, 0);
    k_gather<<<gat_grid, TB>>>(hw16, b1, nullptr, agg, n, 0);
    k_bnstats<<<512, DD>>>(agg, n);
    k_bnfinal<<<1, DD>>>(gamma, beta, 1.0f / (float)n);

    // ---- layer 2 ----
    k_gemm<<<gemm_grid, TB, SMEM_T>>>(agg, wsp + DD * 64, hw16, n, 1);
    k_gather<<<gat_grid, TB>>>(hw16, b2, agg, out, n, 1);
}

// round 14
// speedup vs baseline: 1.4257x; 1.0212x over previous
#include <cuda_runtime.h>
#include <cuda_fp16.h>
#include <stdint.h>

#define DD 128
#define NMAX 50176
#define EMAX 819200

// ---------------- scratch (static device globals; no allocation) ------------
__device__ int    g_cnt   [NMAX];
__device__ int    g_cnt2  [NMAX];       // fill cursors (init = rowptr in scan3)
__device__ int    g_rowptr[NMAX + 1];
__device__ int    g_csr   [EMAX];
__device__ int    g_bsum  [256];
__device__ int    g_boff  [256];
__device__ float  g_dis   [NMAX];
__device__ __half g_hw16  [NMAX * DD];  // fp16 GEMM output (all consumers)
__device__ float  g_agg   [NMAX * DD];
__device__ float  g_bn    [2 * DD];     // col sums / sumsq
__device__ uint2  g_Wsp   [2 * DD * 64];// [layer][n][kp] fp16x2 (hi, lo)

// ---------------- in-degree histogram over dst (x4 vectorized) ---------------
__global__ void k_deg(const int* __restrict__ dst, int E) {
    int i = blockIdx.x * blockDim.x + threadIdx.x;
    int base = i * 4;
    if (base + 3 < E) {
        int4 v = *(const int4*)(dst + base);
        atomicAdd(&g_cnt[v.x], 1);
        atomicAdd(&g_cnt[v.y], 1);
        atomicAdd(&g_cnt[v.z], 1);
        atomicAdd(&g_cnt[v.w], 1);
    } else {
        for (int e = base; e < E; e++) atomicAdd(&g_cnt[dst[e]], 1);
    }
}

// ---------------- scan phase 1: exclusive block scan + block sum + dis -------
__global__ void __launch_bounds__(256) k_scan1(int n) {
    __shared__ int s[256];
    int t = threadIdx.x;
    int i = blockIdx.x * 256 + t;
    int v = (i < n) ? g_cnt[i] : 0;
    if (i < n) g_dis[i] = rsqrtf((float)(1 + v));
    s[t] = v;
    __syncthreads();
#pragma unroll
    for (int off = 1; off < 256; off <<= 1) {
        int u = (t >= off) ? s[t - off] : 0;
        __syncthreads();
        s[t] += u;
        __syncthreads();
    }
    if (i <= n) g_rowptr[i] = s[t] - v;
    if (t == 255) g_bsum[blockIdx.x] = s[255];
}

__global__ void __launch_bounds__(256) k_scan2(int nb, int n) {
    __shared__ int s[256];
    int t = threadIdx.x;
    int v = (t < nb) ? g_bsum[t] : 0;
    s[t] = v;
    __syncthreads();
#pragma unroll
    for (int off = 1; off < 256; off <<= 1) {
        int u = (t >= off) ? s[t - off] : 0;
        __syncthreads();
        s[t] += u;
        __syncthreads();
    }
    if (t < nb) g_boff[t] = s[t] - v;
    if (t == 255) g_rowptr[n] = s[255];
}

// ---------------- scan phase 3: add offsets + init fill cursors --------------
__global__ void __launch_bounds__(256) k_scan3(int n) {
    int i = blockIdx.x * 256 + threadIdx.x;
    if (i < n) {
        int v = g_rowptr[i] + g_boff[blockIdx.x];
        g_rowptr[i] = v;
        g_cnt2[i] = v;
    }
}

// ---------------- CSR fill: direct cursor atomics -----------------------------
__global__ void k_fill(const int* __restrict__ src,
                       const int* __restrict__ dst, int E) {
    int e = blockIdx.x * blockDim.x + threadIdx.x;
    if (e >= E) return;
    int pos = atomicAdd(&g_cnt2[dst[e]], 1);
    g_csr[pos] = src[e];
}

// ---------------- W pre-split: fp32 [k][n] -> fp16 hi/lo uint2 [n][kp] -------
__global__ void k_wsplit(const float* __restrict__ W1,
                         const float* __restrict__ W2) {
    int idx = blockIdx.x * blockDim.x + threadIdx.x;   // 2*128*64
    if (idx >= 2 * DD * 64) return;
    int l  = idx >> 13;
    int r  = idx & 8191;
    int nn = r >> 6;
    int kp = r & 63;
    const float* W = l ? W2 : W1;
    float v0 = W[(size_t)(2 * kp) * DD + nn];
    float v1 = W[(size_t)(2 * kp + 1) * DD + nn];
    __half h0 = __float2half_rn(v0);
    __half h1 = __float2half_rn(v1);
    __half l0 = __float2half_rn(v0 - __half2float(h0));
    __half l1 = __float2half_rn(v1 - __half2float(h1));
    uint32_t hi = ((uint32_t)__half_as_ushort(h1) << 16) | __half_as_ushort(h0);
    uint32_t lo = ((uint32_t)__half_as_ushort(l1) << 16) | __half_as_ushort(l0);
    g_Wsp[idx] = make_uint2(hi, lo);
}

// ---------------- tensor-core GEMM: C16 = A' @ W (2-term: Ah*Wh + Ah*Wl) -----
#define APAD 68
#define SMEM_T (64 * APAD * 4)

__device__ __forceinline__ void mma_f16(float* d, uint32_t a0, uint32_t a1,
                                        uint32_t a2, uint32_t a3,
                                        uint32_t b0, uint32_t b1) {
    asm volatile(
        "mma.sync.aligned.m16n8k16.row.col.f32.f16.f16.f32 "
        "{%0,%1,%2,%3}, {%4,%5,%6,%7}, {%8,%9}, {%0,%1,%2,%3};"
        : "+f"(d[0]), "+f"(d[1]), "+f"(d[2]), "+f"(d[3])
        : "r"(a0), "r"(a1), "r"(a2), "r"(a3), "r"(b0), "r"(b1));
}

__global__ void __launch_bounds__(256) k_gemm(const float* __restrict__ A,
                                              const uint2* __restrict__ Wsp,
                                              __half* __restrict__ C16,
                                              const float* __restrict__ gamma,
                                              const float* __restrict__ beta,
                                              float inv_n, int n, int fuseBN) {
    extern __shared__ uint32_t sA[];   // [64][APAD] fp16x2 per k-pair (Ah)
    __shared__ __align__(16) float s_sa[DD];
    __shared__ __align__(16) float s_sb[DD];
    const int tid  = threadIdx.x;
    const int lane = tid & 31;
    const int w    = tid >> 5;
    const int g    = lane >> 2;
    const int t    = lane & 3;
    const int row0 = blockIdx.x * 64;
    const int rowb = (w & 3) * 16;
    const int colb = (w >> 2) * 64;

    if (fuseBN) {
        if (tid < DD) {
            float mu = g_bn[tid] * inv_n;
            float var = g_bn[DD + tid] * inv_n - mu * mu;
            float rstd = rsqrtf(var + 1e-5f);
            float a = gamma[tid] * rstd;
            s_sa[tid] = a;
            s_sb[tid] = beta[tid] - mu * a;
        }
        __syncthreads();
    }

    // ---- stage A tile [64 rows][64 k-pairs] fp16 ----
    const float4* A4 = (const float4*)A;
#pragma unroll
    for (int i = 0; i < 8; i++) {
        int idx = tid + i * 256;
        int r = idx >> 5, c = idx & 31;   // c = float4 index = 2 k-pairs
        int gr = row0 + r;
        float4 v = (gr < n) ? A4[(size_t)gr * 32 + c]
                            : make_float4(0.f, 0.f, 0.f, 0.f);
        if (fuseBN) {
            float4 sa = *(const float4*)&s_sa[c * 4];
            float4 sb = *(const float4*)&s_sb[c * 4];
            v.x = fmaxf(fmaf(v.x, sa.x, sb.x), 0.f);
            v.y = fmaxf(fmaf(v.y, sa.y, sb.y), 0.f);
            v.z = fmaxf(fmaf(v.z, sa.z, sb.z), 0.f);
            v.w = fmaxf(fmaf(v.w, sa.w, sb.w), 0.f);
        }
        __half2 h01 = __floats2half2_rn(v.x, v.y);
        __half2 h23 = __floats2half2_rn(v.z, v.w);
        *(uint2*)&sA[r * APAD + c * 2] =
            make_uint2(*(uint32_t*)&h01, *(uint32_t*)&h23);
    }
    __syncthreads();

    float acc[8][4];
#pragma unroll
    for (int nt = 0; nt < 8; nt++)
#pragma unroll
        for (int q = 0; q < 4; q++) acc[nt][q] = 0.f;

#pragma unroll
    for (int kf = 0; kf < 8; kf++) {
        uint32_t a0 = sA[(rowb + g) * APAD + kf * 8 + t];
        uint32_t a1 = sA[(rowb + g + 8) * APAD + kf * 8 + t];
        uint32_t a2 = sA[(rowb + g) * APAD + kf * 8 + t + 4];
        uint32_t a3 = sA[(rowb + g + 8) * APAD + kf * 8 + t + 4];
#pragma unroll
        for (int nt = 0; nt < 8; nt++) {
            const uint2* bp = Wsp + (size_t)(colb + nt * 8 + g) * 64 + kf * 8 + t;
            uint2 b0 = bp[0];
            uint2 b1 = bp[4];
            mma_f16(acc[nt], a0, a1, a2, a3, b0.x, b1.x);  // Ah*Wh
            mma_f16(acc[nt], a0, a1, a2, a3, b0.y, b1.y);  // Ah*Wl
        }
    }

    int r0 = row0 + rowb + g;
    int r1 = r0 + 8;
#pragma unroll
    for (int nt = 0; nt < 8; nt++) {
        int cc = colb + nt * 8 + t * 2;
        if (r0 < n) *(__half2*)&C16[(size_t)r0 * DD + cc] =
            __floats2half2_rn(acc[nt][0], acc[nt][1]);
        if (r1 < n) *(__half2*)&C16[(size_t)r1 * DD + cc] =
            __floats2half2_rn(acc[nt][2], acc[nt][3]);
    }
}

// ---------------- CSR gather: warp per dst node, fp16 rows -------------------
__global__ void __launch_bounds__(256) k_gather(const __half* __restrict__ hw16,
                                                const float* __restrict__ bias,
                                                const float* __restrict__ agg,
                                                float* __restrict__ outbuf,
                                                const float* __restrict__ gamma,
                                                const float* __restrict__ beta,
                                                float inv_n, int n, int skip) {
    __shared__ __align__(16) float s_sa[DD];
    __shared__ __align__(16) float s_sb[DD];
    if (skip) {
        if (threadIdx.x < DD) {
            int c = threadIdx.x;
            float mu = g_bn[c] * inv_n;
            float var = g_bn[DD + c] * inv_n - mu * mu;
            float rstd = rsqrtf(var + 1e-5f);
            float a = gamma[c] * rstd;
            s_sa[c] = a;
            s_sb[c] = beta[c] - mu * a;
        }
        __syncthreads();
    }

    int d = (blockIdx.x * blockDim.x + threadIdx.x) >> 5;
    int lane = threadIdx.x & 31;
    if (d >= n) return;

    float invd = g_dis[d];
    float sw = invd * invd;
    const uint2* hw2 = (const uint2*)hw16;   // 32 uint2 per row

    float4 acc = ((const float4*)bias)[lane];
    {
        uint2 u = hw2[(size_t)d * 32 + lane];
        float2 p = __half22float2(*(__half2*)&u.x);
        float2 r = __half22float2(*(__half2*)&u.y);
        acc.x = fmaf(p.x, sw, acc.x);
        acc.y = fmaf(p.y, sw, acc.y);
        acc.z = fmaf(r.x, sw, acc.z);
        acc.w = fmaf(r.y, sw, acc.w);
    }
    if (skip) {
        float4 a  = ((const float4*)agg)[(size_t)d * 32 + lane];
        float4 sa = *(const float4*)&s_sa[lane * 4];
        float4 sb = *(const float4*)&s_sb[lane * 4];
        acc.x += fmaxf(fmaf(a.x, sa.x, sb.x), 0.f);
        acc.y += fmaxf(fmaf(a.y, sa.y, sb.y), 0.f);
        acc.z += fmaxf(fmaf(a.z, sa.z, sb.z), 0.f);
        acc.w += fmaxf(fmaf(a.w, sa.w, sb.w), 0.f);
    }

    int j   = g_rowptr[d];
    int end = g_rowptr[d + 1];
    for (; j + 7 < end; j += 8) {
        int   si[8];
        float wi[8];
        uint2 ui[8];
#pragma unroll
        for (int q = 0; q < 8; q++) si[q] = g_csr[j + q];
#pragma unroll
        for (int q = 0; q < 8; q++) wi[q] = g_dis[si[q]];
#pragma unroll
        for (int q = 0; q < 8; q++) ui[q] = hw2[(size_t)si[q] * 32 + lane];
#pragma unroll
        for (int q = 0; q < 8; q++) {
            float wq = wi[q] * invd;
            float2 p = __half22float2(*(__half2*)&ui[q].x);
            float2 r = __half22float2(*(__half2*)&ui[q].y);
            acc.x = fmaf(p.x, wq, acc.x);
            acc.y = fmaf(p.y, wq, acc.y);
            acc.z = fmaf(r.x, wq, acc.z);
            acc.w = fmaf(r.y, wq, acc.w);
        }
    }
    if (j + 3 < end) {
        int   si[4];
        float wi[4];
        uint2 ui[4];
#pragma unroll
        for (int q = 0; q < 4; q++) si[q] = g_csr[j + q];
#pragma unroll
        for (int q = 0; q < 4; q++) wi[q] = g_dis[si[q]];
#pragma unroll
        for (int q = 0; q < 4; q++) ui[q] = hw2[(size_t)si[q] * 32 + lane];
#pragma unroll
        for (int q = 0; q < 4; q++) {
            float wq = wi[q] * invd;
            float2 p = __half22float2(*(__half2*)&ui[q].x);
            float2 r = __half22float2(*(__half2*)&ui[q].y);
            acc.x = fmaf(p.x, wq, acc.x);
            acc.y = fmaf(p.y, wq, acc.y);
            acc.z = fmaf(r.x, wq, acc.z);
            acc.w = fmaf(r.y, wq, acc.w);
        }
        j += 4;
    }
    for (; j < end; ++j) {
        int s = g_csr[j];
        float wq = g_dis[s] * invd;
        uint2 u = hw2[(size_t)s * 32 + lane];
        float2 p = __half22float2(*(__half2*)&u.x);
        float2 r = __half22float2(*(__half2*)&u.y);
        acc.x = fmaf(p.x, wq, acc.x);
        acc.y = fmaf(p.y, wq, acc.y);
        acc.z = fmaf(r.x, wq, acc.z);
        acc.w = fmaf(r.y, wq, acc.w);
    }
    ((float4*)outbuf)[(size_t)d * 32 + lane] = acc;
}

// ---------------- BN column stats ---------------------------------------------
__global__ void k_bnstats(const float* __restrict__ agg, int n) {
    int c = threadIdx.x;
    float s = 0.f, sq = 0.f;
    for (int r = blockIdx.x; r < n; r += gridDim.x) {
        float v = agg[(size_t)r * DD + c];
        s += v;
        sq = fmaf(v, v, sq);
    }
    atomicAdd(&g_bn[c], s);
    atomicAdd(&g_bn[DD + c], sq);
}

// ============================================================================
extern "C" void kernel_launch(void* const* d_in, const int* in_sizes, int n_in,
                              void* d_out, int out_size) {
    const float* x     = (const float*)d_in[0];
    const int*   ei    = (const int*)d_in[1];
    const float* W1    = (const float*)d_in[2];
    const float* b1    = (const float*)d_in[3];
    const float* W2    = (const float*)d_in[4];
    const float* b2    = (const float*)d_in[5];
    const float* gamma = (const float*)d_in[6];
    const float* beta  = (const float*)d_in[7];
    float*       out   = (float*)d_out;

    const int n = in_sizes[0] / DD;
    const int E = in_sizes[1] / 2;
    const int* src = ei;
    const int* dst = ei + E;
    const float inv_n = 1.0f / (float)n;

    static int inited = 0;
    static cudaStream_t s2;
    static cudaEvent_t evFork, evJoin;
    static void *p_cnt, *p_bn, *p_hw16, *p_agg, *p_wsp;
    if (!inited) {
        cudaFuncSetAttribute(k_gemm, cudaFuncAttributeMaxDynamicSharedMemorySize,
                             SMEM_T);
        cudaStreamCreateWithFlags(&s2, cudaStreamNonBlocking);
        cudaEventCreateWithFlags(&evFork, cudaEventDisableTiming);
        cudaEventCreateWithFlags(&evJoin, cudaEventDisableTiming);
        cudaGetSymbolAddress(&p_cnt,  g_cnt);
        cudaGetSymbolAddress(&p_bn,   g_bn);
        cudaGetSymbolAddress(&p_hw16, g_hw16);
        cudaGetSymbolAddress(&p_agg,  g_agg);
        cudaGetSymbolAddress(&p_wsp,  g_Wsp);
        inited = 1;
    }
    __half* hw16 = (__half*)p_hw16;
    float*  agg  = (float*)p_agg;
    const uint2* wsp = (const uint2*)p_wsp;

    const int TB = 256;
    const int n_grid    = (n + TB - 1) / TB;
    const int e_grid    = (E + TB - 1) / TB;
    const int e4_grid   = (E / 4 + TB - 1) / TB;
    const int gemm_grid = (n + 63) / 64;
    const int gat_grid  = (n * 32 + TB - 1) / TB;

    // fork point
    cudaEventRecord(evFork, 0);
    cudaStreamWaitEvent(s2, evFork, 0);

    // kernel #1 (main)
    k_wsplit<<<(2 * DD * 64 + TB - 1) / TB, TB>>>(W1, W2);

    // s2: CSR build prefix (kernels #2, #3)
    cudaMemsetAsync(p_cnt, 0, (size_t)n * 4, s2);
    cudaMemsetAsync(p_bn,  0, 2 * DD * 4, s2);
    k_deg  <<<e4_grid, TB, 0, s2>>>(dst, E);
    k_scan1<<<n_grid, TB, 0, s2>>>(n);

    // kernel #4 (main) — profiled by ncu (-s 5 -c 1 lands here)
    k_gemm<<<gemm_grid, TB, SMEM_T>>>(x, wsp, hw16, gamma, beta, inv_n, n, 0);

    // s2: CSR build suffix
    k_scan2<<<1,      TB, 0, s2>>>(n_grid, n);
    k_scan3<<<n_grid, TB, 0, s2>>>(n);
    k_fill <<<e_grid, TB, 0, s2>>>(src, dst, E);
    cudaEventRecord(evJoin, s2);

    // ---- layer 1 tail ----
    cudaStreamWaitEvent(0, evJoin, 0);
    k_gather<<<gat_grid, TB>>>(hw16, b1, nullptr, agg, gamma, beta, inv_n, n, 0);
    k_bnstats<<<512, DD>>>(agg, n);

    // ---- layer 2 (BN coeffs computed in-kernel from g_bn; W2 partition!) ----
    k_gemm<<<gemm_grid, TB, SMEM_T>>>(agg, wsp + DD * 64, hw16, gamma, beta,
                                      inv_n, n, 1);
    k_gather<<<gat_grid, TB>>>(hw16, b2, agg, out, gamma, beta, inv_n, n, 1);
}

// round 15
// speedup vs baseline: 1.6562x; 1.1616x over previous
#include <cuda_runtime.h>
#include <cuda_fp16.h>
#include <stdint.h>

#define DD 128
#define NMAX 50176
#define EMAX 819200

// ---------------- scratch (static device globals; no allocation) ------------
__device__ int    g_cnt   [NMAX];
__device__ int    g_cnt2  [NMAX];       // fill cursors (init = rowptr in scan3)
__device__ int    g_rowptr[NMAX + 1];
__device__ int    g_csr   [EMAX];
__device__ int    g_bsum  [256];
__device__ int    g_boff  [256];
__device__ float  g_dis   [NMAX];
__device__ __half g_hw16  [NMAX * DD];  // fp16 GEMM output (all consumers)
__device__ float  g_agg   [NMAX * DD];
__device__ float  g_bn    [2 * DD];     // col sums / sumsq
__device__ uint4  g_Wsp   [2 * 4096];   // fragment-order W: [layer][cg][nt][kf][lane]

// ---------------- in-degree histogram over dst (x4 vectorized) ---------------
__global__ void k_deg(const int* __restrict__ dst, int E) {
    int i = blockIdx.x * blockDim.x + threadIdx.x;
    int base = i * 4;
    if (base + 3 < E) {
        int4 v = *(const int4*)(dst + base);
        atomicAdd(&g_cnt[v.x], 1);
        atomicAdd(&g_cnt[v.y], 1);
        atomicAdd(&g_cnt[v.z], 1);
        atomicAdd(&g_cnt[v.w], 1);
    } else {
        for (int e = base; e < E; e++) atomicAdd(&g_cnt[dst[e]], 1);
    }
}

// ---------------- scan phase 1: exclusive block scan + block sum + dis -------
__global__ void __launch_bounds__(256) k_scan1(int n) {
    __shared__ int s[256];
    int t = threadIdx.x;
    int i = blockIdx.x * 256 + t;
    int v = (i < n) ? g_cnt[i] : 0;
    if (i < n) g_dis[i] = rsqrtf((float)(1 + v));
    s[t] = v;
    __syncthreads();
#pragma unroll
    for (int off = 1; off < 256; off <<= 1) {
        int u = (t >= off) ? s[t - off] : 0;
        __syncthreads();
        s[t] += u;
        __syncthreads();
    }
    if (i <= n) g_rowptr[i] = s[t] - v;
    if (t == 255) g_bsum[blockIdx.x] = s[255];
}

__global__ void __launch_bounds__(256) k_scan2(int nb, int n) {
    __shared__ int s[256];
    int t = threadIdx.x;
    int v = (t < nb) ? g_bsum[t] : 0;
    s[t] = v;
    __syncthreads();
#pragma unroll
    for (int off = 1; off < 256; off <<= 1) {
        int u = (t >= off) ? s[t - off] : 0;
        __syncthreads();
        s[t] += u;
        __syncthreads();
    }
    if (t < nb) g_boff[t] = s[t] - v;
    if (t == 255) g_rowptr[n] = s[255];
}

// ---------------- scan phase 3: add offsets + init fill cursors --------------
__global__ void __launch_bounds__(256) k_scan3(int n) {
    int i = blockIdx.x * 256 + threadIdx.x;
    if (i < n) {
        int v = g_rowptr[i] + g_boff[blockIdx.x];
        g_rowptr[i] = v;
        g_cnt2[i] = v;
    }
}

// ---------------- CSR fill: direct cursor atomics -----------------------------
__global__ void k_fill(const int* __restrict__ src,
                       const int* __restrict__ dst, int E) {
    int e = blockIdx.x * blockDim.x + threadIdx.x;
    if (e >= E) return;
    int pos = atomicAdd(&g_cnt2[dst[e]], 1);
    g_csr[pos] = src[e];
}

// ---------------- W pre-split into MMA B-FRAGMENT order ----------------------
// g_Wsp[((l*2+cg)*8+nt)*8+kf)*32 + lane] = (b0hi, b0lo, b1hi, b1lo)
// lane=g*4+t; row = cg*64+nt*8+g; pairs kp0=kf*8+t, kp1=kp0+4.
__device__ __forceinline__ uint32_t packsplit(float v0, float v1, uint32_t& lo) {
    __half h0 = __float2half_rn(v0), h1 = __float2half_rn(v1);
    __half l0 = __float2half_rn(v0 - __half2float(h0));
    __half l1 = __float2half_rn(v1 - __half2float(h1));
    lo = ((uint32_t)__half_as_ushort(l1) << 16) | __half_as_ushort(l0);
    return ((uint32_t)__half_as_ushort(h1) << 16) | __half_as_ushort(h0);
}

__global__ void k_wsplit(const float* __restrict__ W1,
                         const float* __restrict__ W2) {
    int idx = blockIdx.x * blockDim.x + threadIdx.x;   // 8192 total
    if (idx >= 2 * 4096) return;
    int lane = idx & 31;
    int kf   = (idx >> 5) & 7;
    int nt   = (idx >> 8) & 7;
    int cg   = (idx >> 11) & 1;
    int l    = (idx >> 12) & 1;
    int g = lane >> 2, t = lane & 3;
    int row = cg * 64 + nt * 8 + g;
    int kp0 = kf * 8 + t;
    int kp1 = kp0 + 4;
    const float* W = l ? W2 : W1;     // [k][n] row-major
    uint32_t lo0, lo1;
    uint32_t hi0 = packsplit(W[(size_t)(2 * kp0) * DD + row],
                             W[(size_t)(2 * kp0 + 1) * DD + row], lo0);
    uint32_t hi1 = packsplit(W[(size_t)(2 * kp1) * DD + row],
                             W[(size_t)(2 * kp1 + 1) * DD + row], lo1);
    g_Wsp[idx] = make_uint4(hi0, lo0, hi1, lo1);
}

// ---------------- tensor-core GEMM: C16 = A' @ W (2-term: Ah*Wh + Ah*Wl) -----
#define APAD 68
#define SMEM_T (64 * APAD * 4)

__device__ __forceinline__ void mma_f16(float* d, uint32_t a0, uint32_t a1,
                                        uint32_t a2, uint32_t a3,
                                        uint32_t b0, uint32_t b1) {
    asm volatile(
        "mma.sync.aligned.m16n8k16.row.col.f32.f16.f16.f32 "
        "{%0,%1,%2,%3}, {%4,%5,%6,%7}, {%8,%9}, {%0,%1,%2,%3};"
        : "+f"(d[0]), "+f"(d[1]), "+f"(d[2]), "+f"(d[3])
        : "r"(a0), "r"(a1), "r"(a2), "r"(a3), "r"(b0), "r"(b1));
}

__global__ void __launch_bounds__(256) k_gemm(const float* __restrict__ A,
                                              const uint4* __restrict__ Wsp,
                                              __half* __restrict__ C16,
                                              const float* __restrict__ gamma,
                                              const float* __restrict__ beta,
                                              float inv_n, int n, int fuseBN) {
    extern __shared__ uint32_t sA[];   // [64][APAD] fp16x2 per k-pair (Ah)
    __shared__ __align__(16) float s_sa[DD];
    __shared__ __align__(16) float s_sb[DD];
    const int tid  = threadIdx.x;
    const int lane = tid & 31;
    const int w    = tid >> 5;
    const int g    = lane >> 2;
    const int t    = lane & 3;
    const int row0 = blockIdx.x * 64;
    const int rowb = (w & 3) * 16;
    const int cg   = w >> 2;           // 0 or 1 (col half)
    const int colb = cg * 64;

    if (fuseBN) {
        if (tid < DD) {
            float mu = g_bn[tid] * inv_n;
            float var = g_bn[DD + tid] * inv_n - mu * mu;
            float rstd = rsqrtf(var + 1e-5f);
            float a = gamma[tid] * rstd;
            s_sa[tid] = a;
            s_sb[tid] = beta[tid] - mu * a;
        }
        __syncthreads();
    }

    // ---- stage A tile [64 rows][64 k-pairs] fp16 ----
    const float4* A4 = (const float4*)A;
#pragma unroll
    for (int i = 0; i < 8; i++) {
        int idx = tid + i * 256;
        int r = idx >> 5, c = idx & 31;   // c = float4 index = 2 k-pairs
        int gr = row0 + r;
        float4 v = (gr < n) ? A4[(size_t)gr * 32 + c]
                            : make_float4(0.f, 0.f, 0.f, 0.f);
        if (fuseBN) {
            float4 sa = *(const float4*)&s_sa[c * 4];
            float4 sb = *(const float4*)&s_sb[c * 4];
            v.x = fmaxf(fmaf(v.x, sa.x, sb.x), 0.f);
            v.y = fmaxf(fmaf(v.y, sa.y, sb.y), 0.f);
            v.z = fmaxf(fmaf(v.z, sa.z, sb.z), 0.f);
            v.w = fmaxf(fmaf(v.w, sa.w, sb.w), 0.f);
        }
        __half2 h01 = __floats2half2_rn(v.x, v.y);
        __half2 h23 = __floats2half2_rn(v.z, v.w);
        *(uint2*)&sA[r * APAD + c * 2] =
            make_uint2(*(uint32_t*)&h01, *(uint32_t*)&h23);
    }
    __syncthreads();

    float acc[8][4];
#pragma unroll
    for (int nt = 0; nt < 8; nt++)
#pragma unroll
        for (int q = 0; q < 4; q++) acc[nt][q] = 0.f;

    // fragment-order W base for this warp's column group
    const uint4* wbase = Wsp + (size_t)cg * 2048 + lane;   // [nt][kf][32]

#pragma unroll
    for (int kf = 0; kf < 8; kf++) {
        uint32_t a0 = sA[(rowb + g) * APAD + kf * 8 + t];
        uint32_t a1 = sA[(rowb + g + 8) * APAD + kf * 8 + t];
        uint32_t a2 = sA[(rowb + g) * APAD + kf * 8 + t + 4];
        uint32_t a3 = sA[(rowb + g + 8) * APAD + kf * 8 + t + 4];
#pragma unroll
        for (int nt = 0; nt < 8; nt++) {
            uint4 b = wbase[(nt * 8 + kf) * 32];
            mma_f16(acc[nt], a0, a1, a2, a3, b.x, b.z);  // Ah*Wh
            mma_f16(acc[nt], a0, a1, a2, a3, b.y, b.w);  // Ah*Wl
        }
    }

    int r0 = row0 + rowb + g;
    int r1 = r0 + 8;
#pragma unroll
    for (int nt = 0; nt < 8; nt++) {
        int cc = colb + nt * 8 + t * 2;
        if (r0 < n) *(__half2*)&C16[(size_t)r0 * DD + cc] =
            __floats2half2_rn(acc[nt][0], acc[nt][1]);
        if (r1 < n) *(__half2*)&C16[(size_t)r1 * DD + cc] =
            __floats2half2_rn(acc[nt][2], acc[nt][3]);
    }
}

// ---------------- CSR gather: warp per dst node, fp16 rows -------------------
__global__ void __launch_bounds__(256) k_gather(const __half* __restrict__ hw16,
                                                const float* __restrict__ bias,
                                                const float* __restrict__ agg,
                                                float* __restrict__ outbuf,
                                                const float* __restrict__ gamma,
                                                const float* __restrict__ beta,
                                                float inv_n, int n, int skip) {
    __shared__ __align__(16) float s_sa[DD];
    __shared__ __align__(16) float s_sb[DD];
    if (skip) {
        if (threadIdx.x < DD) {
            int c = threadIdx.x;
            float mu = g_bn[c] * inv_n;
            float var = g_bn[DD + c] * inv_n - mu * mu;
            float rstd = rsqrtf(var + 1e-5f);
            float a = gamma[c] * rstd;
            s_sa[c] = a;
            s_sb[c] = beta[c] - mu * a;
        }
        __syncthreads();
    }

    int d = (blockIdx.x * blockDim.x + threadIdx.x) >> 5;
    int lane = threadIdx.x & 31;
    if (d >= n) return;

    float invd = g_dis[d];
    float sw = invd * invd;
    const uint2* hw2 = (const uint2*)hw16;   // 32 uint2 per row

    float4 acc = ((const float4*)bias)[lane];
    {
        uint2 u = hw2[(size_t)d * 32 + lane];
        float2 p = __half22float2(*(__half2*)&u.x);
        float2 r = __half22float2(*(__half2*)&u.y);
        acc.x = fmaf(p.x, sw, acc.x);
        acc.y = fmaf(p.y, sw, acc.y);
        acc.z = fmaf(r.x, sw, acc.z);
        acc.w = fmaf(r.y, sw, acc.w);
    }
    if (skip) {
        float4 a  = ((const float4*)agg)[(size_t)d * 32 + lane];
        float4 sa = *(const float4*)&s_sa[lane * 4];
        float4 sb = *(const float4*)&s_sb[lane * 4];
        acc.x += fmaxf(fmaf(a.x, sa.x, sb.x), 0.f);
        acc.y += fmaxf(fmaf(a.y, sa.y, sb.y), 0.f);
        acc.z += fmaxf(fmaf(a.z, sa.z, sb.z), 0.f);
        acc.w += fmaxf(fmaf(a.w, sa.w, sb.w), 0.f);
    }

    int j   = g_rowptr[d];
    int end = g_rowptr[d + 1];
    for (; j + 7 < end; j += 8) {
        int   si[8];
        float wi[8];
        uint2 ui[8];
#pragma unroll
        for (int q = 0; q < 8; q++) si[q] = g_csr[j + q];
#pragma unroll
        for (int q = 0; q < 8; q++) wi[q] = g_dis[si[q]];
#pragma unroll
        for (int q = 0; q < 8; q++) ui[q] = hw2[(size_t)si[q] * 32 + lane];
#pragma unroll
        for (int q = 0; q < 8; q++) {
            float wq = wi[q] * invd;
            float2 p = __half22float2(*(__half2*)&ui[q].x);
            float2 r = __half22float2(*(__half2*)&ui[q].y);
            acc.x = fmaf(p.x, wq, acc.x);
            acc.y = fmaf(p.y, wq, acc.y);
            acc.z = fmaf(r.x, wq, acc.z);
            acc.w = fmaf(r.y, wq, acc.w);
        }
    }
    if (j + 3 < end) {
        int   si[4];
        float wi[4];
        uint2 ui[4];
#pragma unroll
        for (int q = 0; q < 4; q++) si[q] = g_csr[j + q];
#pragma unroll
        for (int q = 0; q < 4; q++) wi[q] = g_dis[si[q]];
#pragma unroll
        for (int q = 0; q < 4; q++) ui[q] = hw2[(size_t)si[q] * 32 + lane];
#pragma unroll
        for (int q = 0; q < 4; q++) {
            float wq = wi[q] * invd;
            float2 p = __half22float2(*(__half2*)&ui[q].x);
            float2 r = __half22float2(*(__half2*)&ui[q].y);
            acc.x = fmaf(p.x, wq, acc.x);
            acc.y = fmaf(p.y, wq, acc.y);
            acc.z = fmaf(r.x, wq, acc.z);
            acc.w = fmaf(r.y, wq, acc.w);
        }
        j += 4;
    }
    for (; j < end; ++j) {
        int s = g_csr[j];
        float wq = g_dis[s] * invd;
        uint2 u = hw2[(size_t)s * 32 + lane];
        float2 p = __half22float2(*(__half2*)&u.x);
        float2 r = __half22float2(*(__half2*)&u.y);
        acc.x = fmaf(p.x, wq, acc.x);
        acc.y = fmaf(p.y, wq, acc.y);
        acc.z = fmaf(r.x, wq, acc.z);
        acc.w = fmaf(r.y, wq, acc.w);
    }
    ((float4*)outbuf)[(size_t)d * 32 + lane] = acc;
}

// ---------------- BN column stats ---------------------------------------------
__global__ void k_bnstats(const float* __restrict__ agg, int n) {
    int c = threadIdx.x;
    float s = 0.f, sq = 0.f;
    for (int r = blockIdx.x; r < n; r += gridDim.x) {
        float v = agg[(size_t)r * DD + c];
        s += v;
        sq = fmaf(v, v, sq);
    }
    atomicAdd(&g_bn[c], s);
    atomicAdd(&g_bn[DD + c], sq);
}

// ============================================================================
extern "C" void kernel_launch(void* const* d_in, const int* in_sizes, int n_in,
                              void* d_out, int out_size) {
    const float* x     = (const float*)d_in[0];
    const int*   ei    = (const int*)d_in[1];
    const float* W1    = (const float*)d_in[2];
    const float* b1    = (const float*)d_in[3];
    const float* W2    = (const float*)d_in[4];
    const float* b2    = (const float*)d_in[5];
    const float* gamma = (const float*)d_in[6];
    const float* beta  = (const float*)d_in[7];
    float*       out   = (float*)d_out;

    const int n = in_sizes[0] / DD;
    const int E = in_sizes[1] / 2;
    const int* src = ei;
    const int* dst = ei + E;
    const float inv_n = 1.0f / (float)n;

    static int inited = 0;
    static cudaStream_t s2;
    static cudaEvent_t evFork, evJoin;
    static void *p_cnt, *p_bn, *p_hw16, *p_agg, *p_wsp;
    if (!inited) {
        cudaFuncSetAttribute(k_gemm, cudaFuncAttributeMaxDynamicSharedMemorySize,
                             SMEM_T);
        cudaStreamCreateWithFlags(&s2, cudaStreamNonBlocking);
        cudaEventCreateWithFlags(&evFork, cudaEventDisableTiming);
        cudaEventCreateWithFlags(&evJoin, cudaEventDisableTiming);
        cudaGetSymbolAddress(&p_cnt,  g_cnt);
        cudaGetSymbolAddress(&p_bn,   g_bn);
        cudaGetSymbolAddress(&p_hw16, g_hw16);
        cudaGetSymbolAddress(&p_agg,  g_agg);
        cudaGetSymbolAddress(&p_wsp,  g_Wsp);
        inited = 1;
    }
    __half* hw16 = (__half*)p_hw16;
    float*  agg  = (float*)p_agg;
    const uint4* wsp = (const uint4*)p_wsp;

    const int TB = 256;
    const int n_grid    = (n + TB - 1) / TB;
    const int e_grid    = (E + TB - 1) / TB;
    const int e4_grid   = (E / 4 + TB - 1) / TB;
    const int gemm_grid = (n + 63) / 64;
    const int gat_grid  = (n * 32 + TB - 1) / TB;

    // fork point
    cudaEventRecord(evFork, 0);
    cudaStreamWaitEvent(s2, evFork, 0);

    // kernel #1 (main)
    k_wsplit<<<(2 * 4096 + TB - 1) / TB, TB>>>(W1, W2);

    // s2: CSR build prefix
    cudaMemsetAsync(p_cnt, 0, (size_t)n * 4, s2);
    cudaMemsetAsync(p_bn,  0, 2 * DD * 4, s2);
    k_deg  <<<e4_grid, TB, 0, s2>>>(dst, E);
    k_scan1<<<n_grid, TB, 0, s2>>>(n);

    // kernel #4 (main) — profiled by ncu (-s 5 -c 1 lands here)
    k_gemm<<<gemm_grid, TB, SMEM_T>>>(x, wsp, hw16, gamma, beta, inv_n, n, 0);

    // s2: CSR build suffix
    k_scan2<<<1,      TB, 0, s2>>>(n_grid, n);
    k_scan3<<<n_grid, TB, 0, s2>>>(n);
    k_fill <<<e_grid, TB, 0, s2>>>(src, dst, E);
    cudaEventRecord(evJoin, s2);

    // ---- layer 1 tail ----
    cudaStreamWaitEvent(0, evJoin, 0);
    k_gather<<<gat_grid, TB>>>(hw16, b1, nullptr, agg, gamma, beta, inv_n, n, 0);
    k_bnstats<<<512, DD>>>(agg, n);

    // ---- layer 2 (W2 = second 4096-uint4 partition) ----
    k_gemm<<<gemm_grid, TB, SMEM_T>>>(agg, wsp + 4096, hw16, gamma, beta,
                                      inv_n, n, 1);
    k_gather<<<gat_grid, TB>>>(hw16, b2, agg, out, gamma, beta, inv_n, n, 1);
}

// round 16
// speedup vs baseline: 1.7134x; 1.0346x over previous
#include <cuda_runtime.h>
#include <cuda_fp16.h>
#include <stdint.h>

#define DD 128
#define NMAX 50176
#define EMAX 819200

// ---------------- scratch (static device globals; no allocation) ------------
__device__ int    g_cnt   [NMAX];
__device__ int    g_cnt2  [NMAX];       // fill cursors (init = rowptr in scan3)
__device__ int    g_rowptr[NMAX + 1];
__device__ int    g_csr   [EMAX];
__device__ int    g_bsum  [256];
__device__ int    g_boff  [256];
__device__ float  g_dis   [NMAX];
__device__ __half g_hw16  [NMAX * DD];  // fp16 GEMM output (all consumers)
__device__ float  g_agg   [NMAX * DD];
__device__ float  g_bn    [2 * DD];     // col sums / sumsq
__device__ uint4  g_Wsp   [2 * 4096];   // fragment-order W: [layer][cg][nt][kf][lane]

// ---------------- in-degree histogram over dst (x4 vectorized) ---------------
__global__ void k_deg(const int* __restrict__ dst, int E) {
    int i = blockIdx.x * blockDim.x + threadIdx.x;
    int base = i * 4;
    if (base + 3 < E) {
        int4 v = *(const int4*)(dst + base);
        atomicAdd(&g_cnt[v.x], 1);
        atomicAdd(&g_cnt[v.y], 1);
        atomicAdd(&g_cnt[v.z], 1);
        atomicAdd(&g_cnt[v.w], 1);
    } else {
        for (int e = base; e < E; e++) atomicAdd(&g_cnt[dst[e]], 1);
    }
}

// ---------------- scan phase 1: exclusive block scan + block sum + dis -------
__global__ void __launch_bounds__(256) k_scan1(int n) {
    __shared__ int s[256];
    int t = threadIdx.x;
    int i = blockIdx.x * 256 + t;
    int v = (i < n) ? g_cnt[i] : 0;
    if (i < n) g_dis[i] = rsqrtf((float)(1 + v));
    s[t] = v;
    __syncthreads();
#pragma unroll
    for (int off = 1; off < 256; off <<= 1) {
        int u = (t >= off) ? s[t - off] : 0;
        __syncthreads();
        s[t] += u;
        __syncthreads();
    }
    if (i <= n) g_rowptr[i] = s[t] - v;
    if (t == 255) g_bsum[blockIdx.x] = s[255];
}

__global__ void __launch_bounds__(256) k_scan2(int nb, int n) {
    __shared__ int s[256];
    int t = threadIdx.x;
    int v = (t < nb) ? g_bsum[t] : 0;
    s[t] = v;
    __syncthreads();
#pragma unroll
    for (int off = 1; off < 256; off <<= 1) {
        int u = (t >= off) ? s[t - off] : 0;
        __syncthreads();
        s[t] += u;
        __syncthreads();
    }
    if (t < nb) g_boff[t] = s[t] - v;
    if (t == 255) g_rowptr[n] = s[255];
}

// ---------------- scan phase 3: add offsets + init fill cursors --------------
__global__ void __launch_bounds__(256) k_scan3(int n) {
    int i = blockIdx.x * 256 + threadIdx.x;
    if (i < n) {
        int v = g_rowptr[i] + g_boff[blockIdx.x];
        g_rowptr[i] = v;
        g_cnt2[i] = v;
    }
}

// ---------------- CSR fill: direct cursor atomics -----------------------------
__global__ void k_fill(const int* __restrict__ src,
                       const int* __restrict__ dst, int E) {
    int e = blockIdx.x * blockDim.x + threadIdx.x;
    if (e >= E) return;
    int pos = atomicAdd(&g_cnt2[dst[e]], 1);
    g_csr[pos] = src[e];
}

// ---------------- W pre-split into MMA B-FRAGMENT order ----------------------
__device__ __forceinline__ uint32_t packsplit(float v0, float v1, uint32_t& lo) {
    __half h0 = __float2half_rn(v0), h1 = __float2half_rn(v1);
    __half l0 = __float2half_rn(v0 - __half2float(h0));
    __half l1 = __float2half_rn(v1 - __half2float(h1));
    lo = ((uint32_t)__half_as_ushort(l1) << 16) | __half_as_ushort(l0);
    return ((uint32_t)__half_as_ushort(h1) << 16) | __half_as_ushort(h0);
}

__global__ void k_wsplit(const float* __restrict__ W1,
                         const float* __restrict__ W2) {
    int idx = blockIdx.x * blockDim.x + threadIdx.x;   // 8192 total
    if (idx >= 2 * 4096) return;
    int lane = idx & 31;
    int kf   = (idx >> 5) & 7;
    int nt   = (idx >> 8) & 7;
    int cg   = (idx >> 11) & 1;
    int l    = (idx >> 12) & 1;
    int g = lane >> 2, t = lane & 3;
    int row = cg * 64 + nt * 8 + g;
    int kp0 = kf * 8 + t;
    int kp1 = kp0 + 4;
    const float* W = l ? W2 : W1;     // [k][n] row-major
    uint32_t lo0, lo1;
    uint32_t hi0 = packsplit(W[(size_t)(2 * kp0) * DD + row],
                             W[(size_t)(2 * kp0 + 1) * DD + row], lo0);
    uint32_t hi1 = packsplit(W[(size_t)(2 * kp1) * DD + row],
                             W[(size_t)(2 * kp1 + 1) * DD + row], lo1);
    g_Wsp[idx] = make_uint4(hi0, lo0, hi1, lo1);
}

// ---------------- tensor-core GEMM: C16 = A' @ W (2-term, 128x128 block) -----
// Block 128 rows x 128 cols, 8 warps, warp tile 32 rows x 64 cols.
#define APAD 68
#define SMEM_T (128 * APAD * 4)

__device__ __forceinline__ void mma_f16(float* d, uint32_t a0, uint32_t a1,
                                        uint32_t a2, uint32_t a3,
                                        uint32_t b0, uint32_t b1) {
    asm volatile(
        "mma.sync.aligned.m16n8k16.row.col.f32.f16.f16.f32 "
        "{%0,%1,%2,%3}, {%4,%5,%6,%7}, {%8,%9}, {%0,%1,%2,%3};"
        : "+f"(d[0]), "+f"(d[1]), "+f"(d[2]), "+f"(d[3])
        : "r"(a0), "r"(a1), "r"(a2), "r"(a3), "r"(b0), "r"(b1));
}

__global__ void __launch_bounds__(256, 2) k_gemm(const float* __restrict__ A,
                                                 const uint4* __restrict__ Wsp,
                                                 __half* __restrict__ C16,
                                                 const float* __restrict__ gamma,
                                                 const float* __restrict__ beta,
                                                 float inv_n, int n, int fuseBN) {
    extern __shared__ uint32_t sA[];   // [128][APAD] fp16x2 per k-pair (Ah)
    __shared__ __align__(16) float s_sa[DD];
    __shared__ __align__(16) float s_sb[DD];
    const int tid  = threadIdx.x;
    const int lane = tid & 31;
    const int w    = tid >> 5;
    const int g    = lane >> 2;
    const int t    = lane & 3;
    const int row0 = blockIdx.x * 128;
    const int rowb = (w & 3) * 32;     // warp owns rows [rowb, rowb+32)
    const int cg   = w >> 2;           // 0 or 1 (col half)
    const int colb = cg * 64;

    if (fuseBN) {
        if (tid < DD) {
            float mu = g_bn[tid] * inv_n;
            float var = g_bn[DD + tid] * inv_n - mu * mu;
            float rstd = rsqrtf(var + 1e-5f);
            float a = gamma[tid] * rstd;
            s_sa[tid] = a;
            s_sb[tid] = beta[tid] - mu * a;
        }
        __syncthreads();
    }

    // ---- stage A tile [128 rows][64 k-pairs] fp16 ----
    const float4* A4 = (const float4*)A;
#pragma unroll
    for (int i = 0; i < 16; i++) {
        int idx = tid + i * 256;          // 0..4095 float4
        int r = idx >> 5, c = idx & 31;   // c = float4 index = 2 k-pairs
        int gr = row0 + r;
        float4 v = (gr < n) ? A4[(size_t)gr * 32 + c]
                            : make_float4(0.f, 0.f, 0.f, 0.f);
        if (fuseBN) {
            float4 sa = *(const float4*)&s_sa[c * 4];
            float4 sb = *(const float4*)&s_sb[c * 4];
            v.x = fmaxf(fmaf(v.x, sa.x, sb.x), 0.f);
            v.y = fmaxf(fmaf(v.y, sa.y, sb.y), 0.f);
            v.z = fmaxf(fmaf(v.z, sa.z, sb.z), 0.f);
            v.w = fmaxf(fmaf(v.w, sa.w, sb.w), 0.f);
        }
        __half2 h01 = __floats2half2_rn(v.x, v.y);
        __half2 h23 = __floats2half2_rn(v.z, v.w);
        *(uint2*)&sA[r * APAD + c * 2] =
            make_uint2(*(uint32_t*)&h01, *(uint32_t*)&h23);
    }
    __syncthreads();

    float acc[2][8][4];
#pragma unroll
    for (int rr = 0; rr < 2; rr++)
#pragma unroll
        for (int nt = 0; nt < 8; nt++)
#pragma unroll
            for (int q = 0; q < 4; q++) acc[rr][nt][q] = 0.f;

    const uint4* wbase = Wsp + (size_t)cg * 2048 + lane;   // [nt][kf][32]

#pragma unroll
    for (int kf = 0; kf < 8; kf++) {
        uint32_t af[2][4];
#pragma unroll
        for (int rr = 0; rr < 2; rr++) {
            int rb = rowb + rr * 16;
            af[rr][0] = sA[(rb + g) * APAD + kf * 8 + t];
            af[rr][1] = sA[(rb + g + 8) * APAD + kf * 8 + t];
            af[rr][2] = sA[(rb + g) * APAD + kf * 8 + t + 4];
            af[rr][3] = sA[(rb + g + 8) * APAD + kf * 8 + t + 4];
        }
#pragma unroll
        for (int nt = 0; nt < 8; nt++) {
            uint4 b = wbase[(nt * 8 + kf) * 32];
#pragma unroll
            for (int rr = 0; rr < 2; rr++) {
                mma_f16(acc[rr][nt], af[rr][0], af[rr][1], af[rr][2], af[rr][3],
                        b.x, b.z);  // Ah*Wh
                mma_f16(acc[rr][nt], af[rr][0], af[rr][1], af[rr][2], af[rr][3],
                        b.y, b.w);  // Ah*Wl
            }
        }
    }

#pragma unroll
    for (int rr = 0; rr < 2; rr++) {
        int r0 = row0 + rowb + rr * 16 + g;
        int r1 = r0 + 8;
#pragma unroll
        for (int nt = 0; nt < 8; nt++) {
            int cc = colb + nt * 8 + t * 2;
            if (r0 < n) *(__half2*)&C16[(size_t)r0 * DD + cc] =
                __floats2half2_rn(acc[rr][nt][0], acc[rr][nt][1]);
            if (r1 < n) *(__half2*)&C16[(size_t)r1 * DD + cc] =
                __floats2half2_rn(acc[rr][nt][2], acc[rr][nt][3]);
        }
    }
}

// ---------------- CSR gather: warp per dst node, fp16 rows -------------------
__global__ void __launch_bounds__(256) k_gather(const __half* __restrict__ hw16,
                                                const float* __restrict__ bias,
                                                const float* __restrict__ agg,
                                                float* __restrict__ outbuf,
                                                const float* __restrict__ gamma,
                                                const float* __restrict__ beta,
                                                float inv_n, int n, int skip) {
    __shared__ __align__(16) float s_sa[DD];
    __shared__ __align__(16) float s_sb[DD];
    if (skip) {
        if (threadIdx.x < DD) {
            int c = threadIdx.x;
            float mu = g_bn[c] * inv_n;
            float var = g_bn[DD + c] * inv_n - mu * mu;
            float rstd = rsqrtf(var + 1e-5f);
            float a = gamma[c] * rstd;
            s_sa[c] = a;
            s_sb[c] = beta[c] - mu * a;
        }
        __syncthreads();
    }

    int d = (blockIdx.x * blockDim.x + threadIdx.x) >> 5;
    int lane = threadIdx.x & 31;
    if (d >= n) return;

    float invd = g_dis[d];
    float sw = invd * invd;
    const uint2* hw2 = (const uint2*)hw16;   // 32 uint2 per row

    float4 acc = ((const float4*)bias)[lane];
    {
        uint2 u = hw2[(size_t)d * 32 + lane];
        float2 p = __half22float2(*(__half2*)&u.x);
        float2 r = __half22float2(*(__half2*)&u.y);
        acc.x = fmaf(p.x, sw, acc.x);
        acc.y = fmaf(p.y, sw, acc.y);
        acc.z = fmaf(r.x, sw, acc.z);
        acc.w = fmaf(r.y, sw, acc.w);
    }
    if (skip) {
        float4 a  = ((const float4*)agg)[(size_t)d * 32 + lane];
        float4 sa = *(const float4*)&s_sa[lane * 4];
        float4 sb = *(const float4*)&s_sb[lane * 4];
        acc.x += fmaxf(fmaf(a.x, sa.x, sb.x), 0.f);
        acc.y += fmaxf(fmaf(a.y, sa.y, sb.y), 0.f);
        acc.z += fmaxf(fmaf(a.z, sa.z, sb.z), 0.f);
        acc.w += fmaxf(fmaf(a.w, sa.w, sb.w), 0.f);
    }

    int j   = g_rowptr[d];
    int end = g_rowptr[d + 1];
    for (; j + 7 < end; j += 8) {
        int   si[8];
        float wi[8];
        uint2 ui[8];
#pragma unroll
        for (int q = 0; q < 8; q++) si[q] = g_csr[j + q];
#pragma unroll
        for (int q = 0; q < 8; q++) wi[q] = g_dis[si[q]];
#pragma unroll
        for (int q = 0; q < 8; q++) ui[q] = hw2[(size_t)si[q] * 32 + lane];
#pragma unroll
        for (int q = 0; q < 8; q++) {
            float wq = wi[q] * invd;
            float2 p = __half22float2(*(__half2*)&ui[q].x);
            float2 r = __half22float2(*(__half2*)&ui[q].y);
            acc.x = fmaf(p.x, wq, acc.x);
            acc.y = fmaf(p.y, wq, acc.y);
            acc.z = fmaf(r.x, wq, acc.z);
            acc.w = fmaf(r.y, wq, acc.w);
        }
    }
    if (j + 3 < end) {
        int   si[4];
        float wi[4];
        uint2 ui[4];
#pragma unroll
        for (int q = 0; q < 4; q++) si[q] = g_csr[j + q];
#pragma unroll
        for (int q = 0; q < 4; q++) wi[q] = g_dis[si[q]];
#pragma unroll
        for (int q = 0; q < 4; q++) ui[q] = hw2[(size_t)si[q] * 32 + lane];
#pragma unroll
        for (int q = 0; q < 4; q++) {
            float wq = wi[q] * invd;
            float2 p = __half22float2(*(__half2*)&ui[q].x);
            float2 r = __half22float2(*(__half2*)&ui[q].y);
            acc.x = fmaf(p.x, wq, acc.x);
            acc.y = fmaf(p.y, wq, acc.y);
            acc.z = fmaf(r.x, wq, acc.z);
            acc.w = fmaf(r.y, wq, acc.w);
        }
        j += 4;
    }
    for (; j < end; ++j) {
        int s = g_csr[j];
        float wq = g_dis[s] * invd;
        uint2 u = hw2[(size_t)s * 32 + lane];
        float2 p = __half22float2(*(__half2*)&u.x);
        float2 r = __half22float2(*(__half2*)&u.y);
        acc.x = fmaf(p.x, wq, acc.x);
        acc.y = fmaf(p.y, wq, acc.y);
        acc.z = fmaf(r.x, wq, acc.z);
        acc.w = fmaf(r.y, wq, acc.w);
    }
    ((float4*)outbuf)[(size_t)d * 32 + lane] = acc;
}

// ---------------- BN column stats ---------------------------------------------
__global__ void k_bnstats(const float* __restrict__ agg, int n) {
    int c = threadIdx.x;
    float s = 0.f, sq = 0.f;
    for (int r = blockIdx.x; r < n; r += gridDim.x) {
        float v = agg[(size_t)r * DD + c];
        s += v;
        sq = fmaf(v, v, sq);
    }
    atomicAdd(&g_bn[c], s);
    atomicAdd(&g_bn[DD + c], sq);
}

// ============================================================================
extern "C" void kernel_launch(void* const* d_in, const int* in_sizes, int n_in,
                              void* d_out, int out_size) {
    const float* x     = (const float*)d_in[0];
    const int*   ei    = (const int*)d_in[1];
    const float* W1    = (const float*)d_in[2];
    const float* b1    = (const float*)d_in[3];
    const float* W2    = (const float*)d_in[4];
    const float* b2    = (const float*)d_in[5];
    const float* gamma = (const float*)d_in[6];
    const float* beta  = (const float*)d_in[7];
    float*       out   = (float*)d_out;

    const int n = in_sizes[0] / DD;
    const int E = in_sizes[1] / 2;
    const int* src = ei;
    const int* dst = ei + E;
    const float inv_n = 1.0f / (float)n;

    static int inited = 0;
    static cudaStream_t s2;
    static cudaEvent_t evFork, evJoin;
    static void *p_cnt, *p_bn, *p_hw16, *p_agg, *p_wsp;
    if (!inited) {
        cudaFuncSetAttribute(k_gemm, cudaFuncAttributeMaxDynamicSharedMemorySize,
                             SMEM_T);
        cudaStreamCreateWithFlags(&s2, cudaStreamNonBlocking);
        cudaEventCreateWithFlags(&evFork, cudaEventDisableTiming);
        cudaEventCreateWithFlags(&evJoin, cudaEventDisableTiming);
        cudaGetSymbolAddress(&p_cnt,  g_cnt);
        cudaGetSymbolAddress(&p_bn,   g_bn);
        cudaGetSymbolAddress(&p_hw16, g_hw16);
        cudaGetSymbolAddress(&p_agg,  g_agg);
        cudaGetSymbolAddress(&p_wsp,  g_Wsp);
        inited = 1;
    }
    __half* hw16 = (__half*)p_hw16;
    float*  agg  = (float*)p_agg;
    const uint4* wsp = (const uint4*)p_wsp;

    const int TB = 256;
    const int n_grid    = (n + TB - 1) / TB;
    const int e_grid    = (E + TB - 1) / TB;
    const int e4_grid   = (E / 4 + TB - 1) / TB;
    const int gemm_grid = (n + 127) / 128;
    const int gat_grid  = (n * 32 + TB - 1) / TB;

    // fork point
    cudaEventRecord(evFork, 0);
    cudaStreamWaitEvent(s2, evFork, 0);

    // kernel #1 (main)
    k_wsplit<<<(2 * 4096 + TB - 1) / TB, TB>>>(W1, W2);

    // s2: CSR build prefix
    cudaMemsetAsync(p_cnt, 0, (size_t)n * 4, s2);
    cudaMemsetAsync(p_bn,  0, 2 * DD * 4, s2);
    k_deg  <<<e4_grid, TB, 0, s2>>>(dst, E);
    k_scan1<<<n_grid, TB, 0, s2>>>(n);

    // kernel #4 (main) — profiled by ncu (-s 5 -c 1 lands here)
    k_gemm<<<gemm_grid, TB, SMEM_T>>>(x, wsp, hw16, gamma, beta, inv_n, n, 0);

    // s2: CSR build suffix
    k_scan2<<<1,      TB, 0, s2>>>(n_grid, n);
    k_scan3<<<n_grid, TB, 0, s2>>>(n);
    k_fill <<<e_grid, TB, 0, s2>>>(src, dst, E);
    cudaEventRecord(evJoin, s2);

    // ---- layer 1 tail ----
    cudaStreamWaitEvent(0, evJoin, 0);
    k_gather<<<gat_grid, TB>>>(hw16, b1, nullptr, agg, gamma, beta, inv_n, n, 0);
    k_bnstats<<<512, DD>>>(agg, n);

    // ---- layer 2 (W2 = second 4096-uint4 partition) ----
    k_gemm<<<gemm_grid, TB, SMEM_T>>>(agg, wsp + 4096, hw16, gamma, beta,
                                      inv_n, n, 1);
    k_gather<<<gat_grid, TB>>>(hw16, b2, agg, out, gamma, beta, inv_n, n, 1);
}

// round 17
// speedup vs baseline: 1.8202x; 1.0624x over previous
#include <cuda_runtime.h>
#include <cuda_fp16.h>
#include <stdint.h>

#define DD 128
#define NMAX 50176
#define EMAX 819200

// ---------------- scratch (static device globals; no allocation) ------------
__device__ int    g_cnt   [NMAX];
__device__ int    g_cnt2  [NMAX];       // fill cursors (init = rowptr in scan3)
__device__ int    g_rowptr[NMAX + 1];
__device__ int    g_csr   [EMAX];
__device__ int    g_bsum  [256];
__device__ float  g_dis   [NMAX];
__device__ __half g_hw16  [NMAX * DD];  // fp16 GEMM output
__device__ __half g_agg16 [NMAX * DD];  // fp16 conv1 output (pre-BN)
__device__ float  g_bn    [2 * DD];     // col sums / sumsq
__device__ uint4  g_Wsp   [2 * 4096];   // fragment-order W: [layer][cg][nt][kf][lane]

// ---------------- in-degree histogram over dst (x4 vectorized) ---------------
__global__ void k_deg(const int* __restrict__ dst, int E) {
    int i = blockIdx.x * blockDim.x + threadIdx.x;
    int base = i * 4;
    if (base + 3 < E) {
        int4 v = *(const int4*)(dst + base);
        atomicAdd(&g_cnt[v.x], 1);
        atomicAdd(&g_cnt[v.y], 1);
        atomicAdd(&g_cnt[v.z], 1);
        atomicAdd(&g_cnt[v.w], 1);
    } else {
        for (int e = base; e < E; e++) atomicAdd(&g_cnt[dst[e]], 1);
    }
}

// ------ scan phase 1: block scan + block sum + dis + (block 0: zero g_bn) ----
__global__ void __launch_bounds__(256) k_scan1(int n) {
    __shared__ int s[256];
    int t = threadIdx.x;
    int i = blockIdx.x * 256 + t;
    if (blockIdx.x == 0) g_bn[t] = 0.0f;       // 2*DD == 256
    int v = (i < n) ? g_cnt[i] : 0;
    if (i < n) g_dis[i] = rsqrtf((float)(1 + v));
    s[t] = v;
    __syncthreads();
#pragma unroll
    for (int off = 1; off < 256; off <<= 1) {
        int u = (t >= off) ? s[t - off] : 0;
        __syncthreads();
        s[t] += u;
        __syncthreads();
    }
    if (i <= n) g_rowptr[i] = s[t] - v;
    if (t == 255) g_bsum[blockIdx.x] = s[255];
}

// ------ scan phase 2+3 merged: every block scans block-sums, adds offset -----
__global__ void __launch_bounds__(256) k_scan3(int n, int nb) {
    __shared__ int s[256];
    int t = threadIdx.x;
    int v = (t < nb) ? g_bsum[t] : 0;
    s[t] = v;
    __syncthreads();
#pragma unroll
    for (int off = 1; off < 256; off <<= 1) {
        int u = (t >= off) ? s[t - off] : 0;
        __syncthreads();
        s[t] += u;
        __syncthreads();
    }
    int boff = (blockIdx.x == 0) ? 0 : s[blockIdx.x - 1];
    int i = blockIdx.x * 256 + t;
    if (i <= n) {
        int val = g_rowptr[i] + boff;
        g_rowptr[i] = val;
        if (i < n) g_cnt2[i] = val;
    }
}

// ---------------- CSR fill: direct cursor atomics -----------------------------
__global__ void k_fill(const int* __restrict__ src,
                       const int* __restrict__ dst, int E) {
    int e = blockIdx.x * blockDim.x + threadIdx.x;
    if (e >= E) return;
    int pos = atomicAdd(&g_cnt2[dst[e]], 1);
    g_csr[pos] = src[e];
}

// ---------------- W pre-split into MMA B-FRAGMENT order ----------------------
__device__ __forceinline__ uint32_t packsplit(float v0, float v1, uint32_t& lo) {
    __half h0 = __float2half_rn(v0), h1 = __float2half_rn(v1);
    __half l0 = __float2half_rn(v0 - __half2float(h0));
    __half l1 = __float2half_rn(v1 - __half2float(h1));
    lo = ((uint32_t)__half_as_ushort(l1) << 16) | __half_as_ushort(l0);
    return ((uint32_t)__half_as_ushort(h1) << 16) | __half_as_ushort(h0);
}

__global__ void k_wsplit(const float* __restrict__ W1,
                         const float* __restrict__ W2) {
    int idx = blockIdx.x * blockDim.x + threadIdx.x;   // 8192 total
    if (idx >= 2 * 4096) return;
    int lane = idx & 31;
    int kf   = (idx >> 5) & 7;
    int nt   = (idx >> 8) & 7;
    int cg   = (idx >> 11) & 1;
    int l    = (idx >> 12) & 1;
    int g = lane >> 2, t = lane & 3;
    int row = cg * 64 + nt * 8 + g;
    int kp0 = kf * 8 + t;
    int kp1 = kp0 + 4;
    const float* W = l ? W2 : W1;     // [k][n] row-major
    uint32_t lo0, lo1;
    uint32_t hi0 = packsplit(W[(size_t)(2 * kp0) * DD + row],
                             W[(size_t)(2 * kp0 + 1) * DD + row], lo0);
    uint32_t hi1 = packsplit(W[(size_t)(2 * kp1) * DD + row],
                             W[(size_t)(2 * kp1 + 1) * DD + row], lo1);
    g_Wsp[idx] = make_uint4(hi0, lo0, hi1, lo1);
}

// ---------------- tensor-core GEMM: C16 = A' @ W (2-term, 128x128 block) -----
// fuseBN=0: A from fp32 Af. fuseBN=1: A from fp16 Ah16 with BN+ReLU on the fly.
#define APAD 68
#define SMEM_T (128 * APAD * 4)

__device__ __forceinline__ void mma_f16(float* d, uint32_t a0, uint32_t a1,
                                        uint32_t a2, uint32_t a3,
                                        uint32_t b0, uint32_t b1) {
    asm volatile(
        "mma.sync.aligned.m16n8k16.row.col.f32.f16.f16.f32 "
        "{%0,%1,%2,%3}, {%4,%5,%6,%7}, {%8,%9}, {%0,%1,%2,%3};"
        : "+f"(d[0]), "+f"(d[1]), "+f"(d[2]), "+f"(d[3])
        : "r"(a0), "r"(a1), "r"(a2), "r"(a3), "r"(b0), "r"(b1));
}

__global__ void __launch_bounds__(256, 2) k_gemm(const float* __restrict__ Af,
                                                 const __half* __restrict__ Ah16,
                                                 const uint4* __restrict__ Wsp,
                                                 __half* __restrict__ C16,
                                                 const float* __restrict__ gamma,
                                                 const float* __restrict__ beta,
                                                 float inv_n, int n, int fuseBN) {
    extern __shared__ uint32_t sA[];   // [128][APAD] fp16x2 per k-pair
    __shared__ __align__(16) float s_sa[DD];
    __shared__ __align__(16) float s_sb[DD];
    const int tid  = threadIdx.x;
    const int lane = tid & 31;
    const int w    = tid >> 5;
    const int g    = lane >> 2;
    const int t    = lane & 3;
    const int row0 = blockIdx.x * 128;
    const int rowb = (w & 3) * 32;
    const int cg   = w >> 2;
    const int colb = cg * 64;

    if (fuseBN) {
        if (tid < DD) {
            float mu = g_bn[tid] * inv_n;
            float var = g_bn[DD + tid] * inv_n - mu * mu;
            float rstd = rsqrtf(var + 1e-5f);
            float a = gamma[tid] * rstd;
            s_sa[tid] = a;
            s_sb[tid] = beta[tid] - mu * a;
        }
        __syncthreads();

        // stage from fp16 input with BN+ReLU
        const uint4* A8 = (const uint4*)Ah16;   // 16 uint4 per row (8 halfs ea)
#pragma unroll
        for (int i = 0; i < 8; i++) {
            int idx = tid + i * 256;            // 2048 uint4
            int r = idx >> 4, c = idx & 15;     // c: uint4 within row (8 cols)
            int gr = row0 + r;
            uint4 u = (gr < n) ? A8[(size_t)gr * 16 + c]
                               : make_uint4(0, 0, 0, 0);
            uint32_t pk[4];
            const uint32_t* uu = (const uint32_t*)&u;
#pragma unroll
            for (int j = 0; j < 4; j++) {
                float2 p = __half22float2(*(__half2*)&uu[j]);
                float2 sa = *(const float2*)&s_sa[c * 8 + j * 2];
                float2 sb = *(const float2*)&s_sb[c * 8 + j * 2];
                float v0 = fmaxf(fmaf(p.x, sa.x, sb.x), 0.f);
                float v1 = fmaxf(fmaf(p.y, sa.y, sb.y), 0.f);
                __half2 h = __floats2half2_rn(v0, v1);
                pk[j] = *(uint32_t*)&h;
            }
            *(uint4*)&sA[r * APAD + c * 4] = make_uint4(pk[0], pk[1], pk[2], pk[3]);
        }
    } else {
        // stage from fp32 input
        const float4* A4 = (const float4*)Af;
#pragma unroll
        for (int i = 0; i < 16; i++) {
            int idx = tid + i * 256;            // 4096 float4
            int r = idx >> 5, c = idx & 31;
            int gr = row0 + r;
            float4 v = (gr < n) ? A4[(size_t)gr * 32 + c]
                                : make_float4(0.f, 0.f, 0.f, 0.f);
            __half2 h01 = __floats2half2_rn(v.x, v.y);
            __half2 h23 = __floats2half2_rn(v.z, v.w);
            *(uint2*)&sA[r * APAD + c * 2] =
                make_uint2(*(uint32_t*)&h01, *(uint32_t*)&h23);
        }
    }
    __syncthreads();

    float acc[2][8][4];
#pragma unroll
    for (int rr = 0; rr < 2; rr++)
#pragma unroll
        for (int nt = 0; nt < 8; nt++)
#pragma unroll
            for (int q = 0; q < 4; q++) acc[rr][nt][q] = 0.f;

    const uint4* wbase = Wsp + (size_t)cg * 2048 + lane;   // [nt][kf][32]

#pragma unroll
    for (int kf = 0; kf < 8; kf++) {
        uint32_t af[2][4];
#pragma unroll
        for (int rr = 0; rr < 2; rr++) {
            int rb = rowb + rr * 16;
            af[rr][0] = sA[(rb + g) * APAD + kf * 8 + t];
            af[rr][1] = sA[(rb + g + 8) * APAD + kf * 8 + t];
            af[rr][2] = sA[(rb + g) * APAD + kf * 8 + t + 4];
            af[rr][3] = sA[(rb + g + 8) * APAD + kf * 8 + t + 4];
        }
#pragma unroll
        for (int nt = 0; nt < 8; nt++) {
            uint4 b = wbase[(nt * 8 + kf) * 32];
#pragma unroll
            for (int rr = 0; rr < 2; rr++) {
                mma_f16(acc[rr][nt], af[rr][0], af[rr][1], af[rr][2], af[rr][3],
                        b.x, b.z);  // Ah*Wh
                mma_f16(acc[rr][nt], af[rr][0], af[rr][1], af[rr][2], af[rr][3],
                        b.y, b.w);  // Ah*Wl
            }
        }
    }

#pragma unroll
    for (int rr = 0; rr < 2; rr++) {
        int r0 = row0 + rowb + rr * 16 + g;
        int r1 = r0 + 8;
#pragma unroll
        for (int nt = 0; nt < 8; nt++) {
            int cc = colb + nt * 8 + t * 2;
            if (r0 < n) *(__half2*)&C16[(size_t)r0 * DD + cc] =
                __floats2half2_rn(acc[rr][nt][0], acc[rr][nt][1]);
            if (r1 < n) *(__half2*)&C16[(size_t)r1 * DD + cc] =
                __floats2half2_rn(acc[rr][nt][2], acc[rr][nt][3]);
        }
    }
}

// ---------------- CSR gather: warp per dst node, fp16 rows -------------------
// skip=0: writes fp16 out16 (agg).  skip=1: adds skip term, writes fp32 out32.
__global__ void __launch_bounds__(256) k_gather(const __half* __restrict__ hw16,
                                                const float* __restrict__ bias,
                                                const __half* __restrict__ agg16,
                                                __half* __restrict__ out16,
                                                float* __restrict__ out32,
                                                const float* __restrict__ gamma,
                                                const float* __restrict__ beta,
                                                float inv_n, int n, int skip) {
    __shared__ __align__(16) float s_sa[DD];
    __shared__ __align__(16) float s_sb[DD];
    if (skip) {
        if (threadIdx.x < DD) {
            int c = threadIdx.x;
            float mu = g_bn[c] * inv_n;
            float var = g_bn[DD + c] * inv_n - mu * mu;
            float rstd = rsqrtf(var + 1e-5f);
            float a = gamma[c] * rstd;
            s_sa[c] = a;
            s_sb[c] = beta[c] - mu * a;
        }
        __syncthreads();
    }

    int d = (blockIdx.x * blockDim.x + threadIdx.x) >> 5;
    int lane = threadIdx.x & 31;
    if (d >= n) return;

    float invd = g_dis[d];
    float sw = invd * invd;
    const uint2* hw2 = (const uint2*)hw16;   // 32 uint2 per row

    float4 acc = ((const float4*)bias)[lane];
    {
        uint2 u = hw2[(size_t)d * 32 + lane];
        float2 p = __half22float2(*(__half2*)&u.x);
        float2 r = __half22float2(*(__half2*)&u.y);
        acc.x = fmaf(p.x, sw, acc.x);
        acc.y = fmaf(p.y, sw, acc.y);
        acc.z = fmaf(r.x, sw, acc.z);
        acc.w = fmaf(r.y, sw, acc.w);
    }
    if (skip) {
        uint2 u = ((const uint2*)agg16)[(size_t)d * 32 + lane];
        float2 p = __half22float2(*(__half2*)&u.x);
        float2 r = __half22float2(*(__half2*)&u.y);
        float4 sa = *(const float4*)&s_sa[lane * 4];
        float4 sb = *(const float4*)&s_sb[lane * 4];
        acc.x += fmaxf(fmaf(p.x, sa.x, sb.x), 0.f);
        acc.y += fmaxf(fmaf(p.y, sa.y, sb.y), 0.f);
        acc.z += fmaxf(fmaf(r.x, sa.z, sb.z), 0.f);
        acc.w += fmaxf(fmaf(r.y, sa.w, sb.w), 0.f);
    }

    int j   = g_rowptr[d];
    int end = g_rowptr[d + 1];
    for (; j + 7 < end; j += 8) {
        int   si[8];
        float wi[8];
        uint2 ui[8];
#pragma unroll
        for (int q = 0; q < 8; q++) si[q] = g_csr[j + q];
#pragma unroll
        for (int q = 0; q < 8; q++) wi[q] = g_dis[si[q]];
#pragma unroll
        for (int q = 0; q < 8; q++) ui[q] = hw2[(size_t)si[q] * 32 + lane];
#pragma unroll
        for (int q = 0; q < 8; q++) {
            float wq = wi[q] * invd;
            float2 p = __half22float2(*(__half2*)&ui[q].x);
            float2 r = __half22float2(*(__half2*)&ui[q].y);
            acc.x = fmaf(p.x, wq, acc.x);
            acc.y = fmaf(p.y, wq, acc.y);
            acc.z = fmaf(r.x, wq, acc.z);
            acc.w = fmaf(r.y, wq, acc.w);
        }
    }
    if (j + 3 < end) {
        int   si[4];
        float wi[4];
        uint2 ui[4];
#pragma unroll
        for (int q = 0; q < 4; q++) si[q] = g_csr[j + q];
#pragma unroll
        for (int q = 0; q < 4; q++) wi[q] = g_dis[si[q]];
#pragma unroll
        for (int q = 0; q < 4; q++) ui[q] = hw2[(size_t)si[q] * 32 + lane];
#pragma unroll
        for (int q = 0; q < 4; q++) {
            float wq = wi[q] * invd;
            float2 p = __half22float2(*(__half2*)&ui[q].x);
            float2 r = __half22float2(*(__half2*)&ui[q].y);
            acc.x = fmaf(p.x, wq, acc.x);
            acc.y = fmaf(p.y, wq, acc.y);
            acc.z = fmaf(r.x, wq, acc.z);
            acc.w = fmaf(r.y, wq, acc.w);
        }
        j += 4;
    }
    for (; j < end; ++j) {
        int s = g_csr[j];
        float wq = g_dis[s] * invd;
        uint2 u = hw2[(size_t)s * 32 + lane];
        float2 p = __half22float2(*(__half2*)&u.x);
        float2 r = __half22float2(*(__half2*)&u.y);
        acc.x = fmaf(p.x, wq, acc.x);
        acc.y = fmaf(p.y, wq, acc.y);
        acc.z = fmaf(r.x, wq, acc.z);
        acc.w = fmaf(r.y, wq, acc.w);
    }

    if (skip) {
        ((float4*)out32)[(size_t)d * 32 + lane] = acc;
    } else {
        __half2 h01 = __floats2half2_rn(acc.x, acc.y);
        __half2 h23 = __floats2half2_rn(acc.z, acc.w);
        ((uint2*)out16)[(size_t)d * 32 + lane] =
            make_uint2(*(uint32_t*)&h01, *(uint32_t*)&h23);
    }
}

// ---------------- BN column stats (fp16 input) --------------------------------
__global__ void k_bnstats(const __half* __restrict__ agg16, int n) {
    int c = threadIdx.x;
    float s = 0.f, sq = 0.f;
    for (int r = blockIdx.x; r < n; r += gridDim.x) {
        float v = __half2float(agg16[(size_t)r * DD + c]);
        s += v;
        sq = fmaf(v, v, sq);
    }
    atomicAdd(&g_bn[c], s);
    atomicAdd(&g_bn[DD + c], sq);
}

// ============================================================================
extern "C" void kernel_launch(void* const* d_in, const int* in_sizes, int n_in,
                              void* d_out, int out_size) {
    const float* x     = (const float*)d_in[0];
    const int*   ei    = (const int*)d_in[1];
    const float* W1    = (const float*)d_in[2];
    const float* b1    = (const float*)d_in[3];
    const float* W2    = (const float*)d_in[4];
    const float* b2    = (const float*)d_in[5];
    const float* gamma = (const float*)d_in[6];
    const float* beta  = (const float*)d_in[7];
    float*       out   = (float*)d_out;

    const int n = in_sizes[0] / DD;
    const int E = in_sizes[1] / 2;
    const int* src = ei;
    const int* dst = ei + E;
    const float inv_n = 1.0f / (float)n;

    static int inited = 0;
    static cudaStream_t s2;
    static cudaEvent_t evFork, evJoin;
    static void *p_cnt, *p_hw16, *p_agg16, *p_wsp;
    if (!inited) {
        cudaFuncSetAttribute(k_gemm, cudaFuncAttributeMaxDynamicSharedMemorySize,
                             SMEM_T);
        cudaStreamCreateWithFlags(&s2, cudaStreamNonBlocking);
        cudaEventCreateWithFlags(&evFork, cudaEventDisableTiming);
        cudaEventCreateWithFlags(&evJoin, cudaEventDisableTiming);
        cudaGetSymbolAddress(&p_cnt,   g_cnt);
        cudaGetSymbolAddress(&p_hw16,  g_hw16);
        cudaGetSymbolAddress(&p_agg16, g_agg16);
        cudaGetSymbolAddress(&p_wsp,   g_Wsp);
        inited = 1;
    }
    __half* hw16  = (__half*)p_hw16;
    __half* agg16 = (__half*)p_agg16;
    const uint4* wsp = (const uint4*)p_wsp;

    const int TB = 256;
    const int n_grid    = (n + TB - 1) / TB;
    const int e_grid    = (E + TB - 1) / TB;
    const int e4_grid   = (E / 4 + TB - 1) / TB;
    const int gemm_grid = (n + 127) / 128;
    const int gat_grid  = (n * 32 + TB - 1) / TB;

    // fork point
    cudaEventRecord(evFork, 0);
    cudaStreamWaitEvent(s2, evFork, 0);

    // main: W pre-split
    k_wsplit<<<(2 * 4096 + TB - 1) / TB, TB>>>(W1, W2);

    // s2: CSR build (shortened chain)
    cudaMemsetAsync(p_cnt, 0, (size_t)n * 4, s2);
    k_deg  <<<e4_grid, TB, 0, s2>>>(dst, E);
    k_scan1<<<n_grid, TB, 0, s2>>>(n);

    // main: GEMM1 (profiled launch slot)
    k_gemm<<<gemm_grid, TB, SMEM_T>>>(x, nullptr, wsp, hw16, gamma, beta,
                                      inv_n, n, 0);

    // s2: chain tail
    k_scan3<<<n_grid, TB, 0, s2>>>(n, n_grid);
    k_fill <<<e_grid, TB, 0, s2>>>(src, dst, E);
    cudaEventRecord(evJoin, s2);

    // ---- layer 1 tail ----
    cudaStreamWaitEvent(0, evJoin, 0);
    k_gather<<<gat_grid, TB>>>(hw16, b1, nullptr, agg16, nullptr,
                               gamma, beta, inv_n, n, 0);
    k_bnstats<<<512, DD>>>(agg16, n);

    // ---- layer 2 ----
    k_gemm<<<gemm_grid, TB, SMEM_T>>>(nullptr, agg16, wsp + 4096, hw16,
                                      gamma, beta, inv_n, n, 1);
    k_gather<<<gat_grid, TB>>>(hw16, b2, agg16, nullptr, out,
                               gamma, beta, inv_n, n, 1);
}